// round 2
// baseline (speedup 1.0000x reference)
#include <cuda_runtime.h>
#include <stdint.h>

#define NN    50000
#define NEDGE 1600000
#define NDIM  1024
#define HID   128
#define CAP   128   // max degree slots per node; Binomial(1.6M,1/50k): P(deg>128) ~ 0

// ---------------- scratch (static device globals; no allocation) ----------------
__device__ float d_h [(size_t)NN * HID];   // relu(x @ proj_w.T + b)
__device__ float d_hL[(size_t)NN * HID];   // h @ lin_l_w.T
__device__ float d_hR[(size_t)NN * HID];   // h @ lin_r_w.T + lin_l_b
__device__ int   d_cnt[NN];                // per-dst degree
__device__ int   d_slot[(size_t)NN * CAP]; // per-dst src lists
__device__ float d_pool[HID];              // global mean-pool accumulator

// ---------------- K0: zero counters + pool ----------------
__global__ void zero_kernel() {
    int i = blockIdx.x * blockDim.x + threadIdx.x;
    if (i < NN)  d_cnt[i] = 0;
    if (i < HID) d_pool[i] = 0.f;
}

// ---------------- generic GEMM: Y[N,128] = act(X[N,K] @ W[128,K]^T + bias) ----------------
// BM=128, BN=128, BK=16, 256 threads, 8x8 thread tile.
template<int K, bool RELU, bool HASB>
__global__ __launch_bounds__(256)
void gemm128_kernel(const float* __restrict__ X,
                    const float* __restrict__ W,
                    const float* __restrict__ bias,
                    float* __restrict__ Y, int N)
{
    __shared__ float As[16][132];
    __shared__ float Bs[16][132];

    const int tid = threadIdx.x;
    const int tx  = tid & 15;     // col group
    const int ty  = tid >> 4;     // row group
    const int row0 = blockIdx.x * 128;

    float acc[8][8];
    #pragma unroll
    for (int i = 0; i < 8; i++)
        #pragma unroll
        for (int j = 0; j < 8; j++) acc[i][j] = 0.f;

    for (int k0 = 0; k0 < K; k0 += 16) {
        // load A tile (128 x 16) and B tile (128 x 16), transposed into smem
        #pragma unroll
        for (int l = 0; l < 2; l++) {
            int idx = tid + l * 256;         // [0,512)
            int m   = idx >> 2;              // [0,128)
            int kq  = (idx & 3) * 4;         // {0,4,8,12}
            int gm  = row0 + m;
            float4 v = make_float4(0.f, 0.f, 0.f, 0.f);
            if (gm < N) v = *(const float4*)&X[(size_t)gm * K + k0 + kq];
            As[kq + 0][m] = v.x; As[kq + 1][m] = v.y;
            As[kq + 2][m] = v.z; As[kq + 3][m] = v.w;
            float4 w = *(const float4*)&W[(size_t)m * K + k0 + kq];
            Bs[kq + 0][m] = w.x; Bs[kq + 1][m] = w.y;
            Bs[kq + 2][m] = w.z; Bs[kq + 3][m] = w.w;
        }
        __syncthreads();

        #pragma unroll
        for (int kk = 0; kk < 16; kk++) {
            float a[8], b[8];
            *(float4*)&a[0] = *(const float4*)&As[kk][ty * 8];
            *(float4*)&a[4] = *(const float4*)&As[kk][ty * 8 + 4];
            *(float4*)&b[0] = *(const float4*)&Bs[kk][tx * 8];
            *(float4*)&b[4] = *(const float4*)&Bs[kk][tx * 8 + 4];
            #pragma unroll
            for (int i = 0; i < 8; i++)
                #pragma unroll
                for (int j = 0; j < 8; j++)
                    acc[i][j] = fmaf(a[i], b[j], acc[i][j]);
        }
        __syncthreads();
    }

    // epilogue
    #pragma unroll
    for (int i = 0; i < 8; i++) {
        int gm = row0 + ty * 8 + i;
        if (gm >= N) break;
        #pragma unroll
        for (int j4 = 0; j4 < 2; j4++) {
            int jc = tx * 8 + j4 * 4;
            float4 o;
            o.x = acc[i][j4 * 4 + 0];
            o.y = acc[i][j4 * 4 + 1];
            o.z = acc[i][j4 * 4 + 2];
            o.w = acc[i][j4 * 4 + 3];
            if (HASB) {
                o.x += bias[jc + 0]; o.y += bias[jc + 1];
                o.z += bias[jc + 2]; o.w += bias[jc + 3];
            }
            if (RELU) {
                o.x = fmaxf(o.x, 0.f); o.y = fmaxf(o.y, 0.f);
                o.z = fmaxf(o.z, 0.f); o.w = fmaxf(o.w, 0.f);
            }
            *(float4*)&Y[(size_t)gm * HID + jc] = o;
        }
    }
}

// ---------------- K3: bucket edges by dst (int atomics only) ----------------
// edge_index is int32 on device (JAX x64 is disabled; jnp.int64 request
// silently produces int32). Guard ranges so a wrong dtype assumption shows
// up as rel_err, not an illegal access.
__global__ void edge_bucket_kernel(const int* __restrict__ ei) {
    int i = blockIdx.x * blockDim.x + threadIdx.x;
    if (i >= NEDGE) return;
    int src = ei[i];
    int dst = ei[NEDGE + i];
    if ((unsigned)src >= NN || (unsigned)dst >= NN) return;
    int pos = atomicAdd(&d_cnt[dst], 1);
    if (pos < CAP) d_slot[(size_t)dst * CAP + pos] = src;
}

// ---------------- K4: warp-per-node gather + combine + LN + relu + pool ----------------
__global__ __launch_bounds__(256)
void gather_ln_pool_kernel(const float* __restrict__ lng,
                           const float* __restrict__ lnb)
{
    const int lane   = threadIdx.x & 31;
    const int warp   = threadIdx.x >> 5;
    const int nwarps = blockDim.x >> 5;   // 8

    const float4* HL4 = (const float4*)d_hL;
    const float4* HR4 = (const float4*)d_hR;
    const float4  g4  = ((const float4*)lng)[lane];
    const float4  b4  = ((const float4*)lnb)[lane];

    float4 pacc = make_float4(0.f, 0.f, 0.f, 0.f);

    for (int node = blockIdx.x * nwarps + warp; node < NN;
         node += gridDim.x * nwarps)
    {
        int deg = d_cnt[node];
        int dn  = min(deg, CAP);

        float4 acc = make_float4(0.f, 0.f, 0.f, 0.f);
        for (int base = 0; base < dn; base += 32) {
            int myslot = 0;
            if (base + lane < dn) myslot = d_slot[(size_t)node * CAP + base + lane];
            int m = min(32, dn - base);
            for (int j = 0; j < m; j++) {
                int s = __shfl_sync(0xffffffffu, myslot, j);
                float4 v = HL4[(size_t)s * 32 + lane];
                acc.x += v.x; acc.y += v.y; acc.z += v.z; acc.w += v.w;
            }
        }

        float inv = 1.f / fmaxf((float)deg, 1.f);
        float4 hr = HR4[(size_t)node * 32 + lane];
        float4 y;
        y.x = fmaf(acc.x, inv, hr.x);
        y.y = fmaf(acc.y, inv, hr.y);
        y.z = fmaf(acc.z, inv, hr.z);
        y.w = fmaf(acc.w, inv, hr.w);

        // LayerNorm over 128 features (warp reduce of s1, s2)
        float s1 = y.x + y.y + y.z + y.w;
        float s2 = y.x * y.x + y.y * y.y + y.z * y.z + y.w * y.w;
        #pragma unroll
        for (int o = 16; o > 0; o >>= 1) {
            s1 += __shfl_xor_sync(0xffffffffu, s1, o);
            s2 += __shfl_xor_sync(0xffffffffu, s2, o);
        }
        float mu   = s1 * (1.f / 128.f);
        float var  = s2 * (1.f / 128.f) - mu * mu;
        float rstd = rsqrtf(var + 1e-5f);

        float4 r;
        r.x = fmaxf((y.x - mu) * rstd * g4.x + b4.x, 0.f);
        r.y = fmaxf((y.y - mu) * rstd * g4.y + b4.y, 0.f);
        r.z = fmaxf((y.z - mu) * rstd * g4.z + b4.z, 0.f);
        r.w = fmaxf((y.w - mu) * rstd * g4.w + b4.w, 0.f);

        pacc.x += r.x; pacc.y += r.y; pacc.z += r.z; pacc.w += r.w;
    }

    // block reduce pool partials, one atomicAdd per feature per block
    __shared__ float sp[8][128];
    ((float4*)sp[warp])[lane] = pacc;
    __syncthreads();
    int t = threadIdx.x;
    if (t < HID) {
        float s = 0.f;
        #pragma unroll
        for (int w = 0; w < 8; w++) s += sp[w][t];
        atomicAdd(&d_pool[t], s);
    }
}

// ---------------- K5: final linear on pooled mean ----------------
__global__ void final_kernel(const float* __restrict__ ow,
                             const float* __restrict__ ob,
                             float* __restrict__ out)
{
    __shared__ float g[128];
    int t = threadIdx.x;
    g[t] = d_pool[t] * (1.f / (float)NN);
    __syncthreads();
    float s = ob[t];
    #pragma unroll 8
    for (int f = 0; f < 128; f++)
        s = fmaf(g[f], ow[(size_t)t * 128 + f], s);
    out[t] = s;
}

// ---------------- launch ----------------
extern "C" void kernel_launch(void* const* d_in, const int* in_sizes, int n_in,
                              void* d_out, int out_size)
{
    const float* x       = (const float*)d_in[0];
    const int*   ei      = (const int*)d_in[1];     // int32! (JAX x64 disabled)
    const float* proj_w  = (const float*)d_in[2];
    const float* proj_b  = (const float*)d_in[3];
    const float* lin_l_w = (const float*)d_in[4];
    const float* lin_l_b = (const float*)d_in[5];
    const float* lin_r_w = (const float*)d_in[6];
    const float* ln_g    = (const float*)d_in[7];
    const float* ln_b    = (const float*)d_in[8];
    const float* out_w   = (const float*)d_in[9];
    const float* out_b   = (const float*)d_in[10];
    float* out = (float*)d_out;

    float *ph, *phL, *phR;
    cudaGetSymbolAddress((void**)&ph,  d_h);
    cudaGetSymbolAddress((void**)&phL, d_hL);
    cudaGetSymbolAddress((void**)&phR, d_hR);

    // K0: zero counters + pool
    zero_kernel<<<(NN + 255) / 256, 256>>>();

    // K1: h = relu(x @ proj_w.T + proj_b)
    int gblocks = (NN + 127) / 128;
    gemm128_kernel<NDIM, true,  true ><<<gblocks, 256>>>(x,  proj_w,  proj_b,  ph,  NN);

    // K2: hL = h @ lin_l_w.T ; hR = h @ lin_r_w.T + lin_l_b
    gemm128_kernel<HID,  false, false><<<gblocks, 256>>>(ph, lin_l_w, nullptr, phL, NN);
    gemm128_kernel<HID,  false, true ><<<gblocks, 256>>>(ph, lin_r_w, lin_l_b, phR, NN);

    // K3: bucket edges by dst
    edge_bucket_kernel<<<(NEDGE + 255) / 256, 256>>>(ei);

    // K4: gather + mean + combine + LN + relu + pooled sum
    gather_ln_pool_kernel<<<592, 256>>>(ln_g, ln_b);

    // K5: final linear
    final_kernel<<<1, 128>>>(out_w, out_b, out);
}

// round 5
// speedup vs baseline: 1.4886x; 1.4886x over previous
#include <cuda_runtime.h>
#include <cuda_bf16.h>
#include <stdint.h>

#define NN    50000
#define NEDGE 1600000
#define NDIM  1024
#define HID   128
#define CAP   128

// ================= scratch =================
__device__ __nv_bfloat16 d_hHi[(size_t)NN * HID];
__device__ __nv_bfloat16 d_hLo[(size_t)NN * HID];
__device__ __nv_bfloat16 d_hLb[(size_t)NN * HID];   // hL bf16 (gather operand)
__device__ float         d_hR [(size_t)NN * HID];   // h @ lin_r_w.T + lin_l_b
__device__ int           d_cnt[NN];
__device__ int           d_slot[(size_t)NN * CAP];
__device__ float         d_pool[HID];

// ================= helpers =================
__device__ __forceinline__ uint32_t smem_u32(const void* p) {
    uint32_t a;
    asm("{ .reg .u64 t; cvta.to.shared.u64 t, %1; cvt.u32.u64 %0, t; }" : "=r"(a) : "l"(p));
    return a;
}
#define SWZ128(o) ((o) ^ (((o) >> 3) & 0x70))

__device__ __forceinline__ uint32_t packbf2(__nv_bfloat16 a, __nv_bfloat16 b) {
    return (uint32_t)__bfloat16_as_ushort(a) | ((uint32_t)__bfloat16_as_ushort(b) << 16);
}
__device__ __forceinline__ void split4(float4 v, uint2& hi, uint2& lo) {
    __nv_bfloat16 hx = __float2bfloat16(v.x), hy = __float2bfloat16(v.y);
    __nv_bfloat16 hz = __float2bfloat16(v.z), hw = __float2bfloat16(v.w);
    __nv_bfloat16 lx = __float2bfloat16(v.x - __bfloat162float(hx));
    __nv_bfloat16 ly = __float2bfloat16(v.y - __bfloat162float(hy));
    __nv_bfloat16 lz = __float2bfloat16(v.z - __bfloat162float(hz));
    __nv_bfloat16 lw = __float2bfloat16(v.w - __bfloat162float(hw));
    hi.x = packbf2(hx, hy); hi.y = packbf2(hz, hw);
    lo.x = packbf2(lx, ly); lo.y = packbf2(lz, lw);
}

#define LDSM_X4(r, a) \
    asm volatile("ldmatrix.sync.aligned.m8n8.x4.shared.b16 {%0,%1,%2,%3}, [%4];" \
        : "=r"((r)[0]), "=r"((r)[1]), "=r"((r)[2]), "=r"((r)[3]) : "r"(a))
// NON-trans: W tile is [n rows][k cols]; lane j then holds [n=j/4][k=(j%4)*2+{0,1}]
// which is exactly the mma.row.col B-fragment layout.
#define LDSM_X2(r, a) \
    asm volatile("ldmatrix.sync.aligned.m8n8.x2.shared.b16 {%0,%1}, [%2];" \
        : "=r"((r)[0]), "=r"((r)[1]) : "r"(a))
#define MMA_BF16(d, a, b) \
    asm volatile("mma.sync.aligned.m16n8k16.row.col.f32.bf16.bf16.f32 " \
        "{%0,%1,%2,%3}, {%4,%5,%6,%7}, {%8,%9}, {%0,%1,%2,%3};" \
        : "+f"((d)[0]), "+f"((d)[1]), "+f"((d)[2]), "+f"((d)[3]) \
        : "r"((a)[0]), "r"((a)[1]), "r"((a)[2]), "r"((a)[3]), "r"((b)[0]), "r"((b)[1]))

// A-frag ldmatrix address: tile [128 rows][64 bf16], row stride 128B, SW128
__device__ __forceinline__ uint32_t addrA(uint32_t base, int mi, int ks, int lane) {
    int row  = mi * 16 + (lane & 15);
    int kb   = ks * 32 + ((lane >> 4) << 4);
    return base + SWZ128((uint32_t)(row * 128 + kb));
}
// B-frag address: W tile [128 n][64 k]; matrix0 = k-lo half, matrix1 = k-hi half
__device__ __forceinline__ uint32_t addrB(uint32_t base, int ni, int ks, int lane) {
    int row = ni * 8 + (lane & 7);
    int kb  = ks * 32 + (((lane >> 3) & 1) << 4);
    return base + SWZ128((uint32_t)(row * 128 + kb));
}

// ================= K0 =================
__global__ void zero_kernel() {
    int i = blockIdx.x * blockDim.x + threadIdx.x;
    if (i < NN)  d_cnt[i] = 0;
    if (i < HID) d_pool[i] = 0.f;
}

// ================= K1: h = relu(x @ proj_w.T + b), mma.sync bf16-split x3 =================
// smem: Ahi 0, Alo 16K, Bhi 32K, Blo 48K (each [128][64] bf16, SW128)
#define K1_SMEM 65536

__global__ __launch_bounds__(256)
void proj_mma_kernel(const float* __restrict__ X, const float* __restrict__ W,
                     const float* __restrict__ bias)
{
    extern __shared__ char smem[];
    const uint32_t sb = smem_u32(smem);
    const int tid  = threadIdx.x;
    const int lane = tid & 31;
    const int wid  = tid >> 5;
    const int wm   = wid & 1;        // 2 warp-rows  (64 rows each)
    const int wn   = wid >> 1;       // 4 warp-cols  (32 cols each)
    const int row0 = blockIdx.x * 128;

    float acc[4][4][4];
    #pragma unroll
    for (int i = 0; i < 4; i++)
        #pragma unroll
        for (int j = 0; j < 4; j++)
            #pragma unroll
            for (int q = 0; q < 4; q++) acc[i][j][q] = 0.f;

    const uint32_t aHi = sb, aLo = sb + 16384, bHi = sb + 32768, bLo = sb + 49152;

    #pragma unroll 1
    for (int c = 0; c < 16; c++) {
        const int kc = c * 64;
        // A chunk: 128 rows x 64 fp32 -> bf16 hi/lo
        #pragma unroll
        for (int it = 0; it < 8; it++) {
            int e = tid + it * 256;
            int r = e >> 4, c4 = (e & 15) << 2;
            float4 v = make_float4(0.f, 0.f, 0.f, 0.f);
            int gm = row0 + r;
            if (gm < NN) v = *(const float4*)&X[(size_t)gm * NDIM + kc + c4];
            uint2 hi, lo; split4(v, hi, lo);
            uint32_t sw = SWZ128((uint32_t)(r * 128 + c4 * 2));
            *(uint2*)(smem + sw)         = hi;
            *(uint2*)(smem + 16384 + sw) = lo;
        }
        // W chunk: 128 rows x 64 fp32 -> bf16 hi/lo
        #pragma unroll
        for (int it = 0; it < 8; it++) {
            int e = tid + it * 256;
            int r = e >> 4, c4 = (e & 15) << 2;
            float4 v = *(const float4*)&W[(size_t)r * NDIM + kc + c4];
            uint2 hi, lo; split4(v, hi, lo);
            uint32_t sw = SWZ128((uint32_t)(r * 128 + c4 * 2));
            *(uint2*)(smem + 32768 + sw) = hi;
            *(uint2*)(smem + 49152 + sw) = lo;
        }
        __syncthreads();

        #pragma unroll
        for (int ks = 0; ks < 4; ks++) {
            uint32_t ahi[4][4], alo[4][4];
            #pragma unroll
            for (int mi = 0; mi < 4; mi++) {
                LDSM_X4(ahi[mi], addrA(aHi, wm * 4 + mi, ks, lane));
                LDSM_X4(alo[mi], addrA(aLo, wm * 4 + mi, ks, lane));
            }
            #pragma unroll
            for (int ni = 0; ni < 4; ni++) {
                uint32_t bh[2], bl[2];
                LDSM_X2(bh, addrB(bHi, wn * 4 + ni, ks, lane));
                LDSM_X2(bl, addrB(bLo, wn * 4 + ni, ks, lane));
                #pragma unroll
                for (int mi = 0; mi < 4; mi++) {
                    MMA_BF16(acc[mi][ni], ahi[mi], bh);
                    MMA_BF16(acc[mi][ni], ahi[mi], bl);
                    MMA_BF16(acc[mi][ni], alo[mi], bh);
                }
            }
        }
        __syncthreads();
    }

    // epilogue: +bias, relu, split to bf16 hi/lo, store
    #pragma unroll
    for (int ni = 0; ni < 4; ni++) {
        int cc = wn * 32 + ni * 8 + (lane & 3) * 2;
        float b0 = bias[cc], b1 = bias[cc + 1];
        #pragma unroll
        for (int mi = 0; mi < 4; mi++) {
            int r0 = row0 + wm * 64 + mi * 16 + (lane >> 2);
            #pragma unroll
            for (int half = 0; half < 2; half++) {
                int r = r0 + half * 8;
                if (r < NN) {
                    float v0 = fmaxf(acc[mi][ni][half * 2 + 0] + b0, 0.f);
                    float v1 = fmaxf(acc[mi][ni][half * 2 + 1] + b1, 0.f);
                    __nv_bfloat16 h0 = __float2bfloat16(v0), h1 = __float2bfloat16(v1);
                    __nv_bfloat16 l0 = __float2bfloat16(v0 - __bfloat162float(h0));
                    __nv_bfloat16 l1 = __float2bfloat16(v1 - __bfloat162float(h1));
                    size_t off = (size_t)r * HID + cc;
                    *(uint32_t*)&d_hHi[off] = packbf2(h0, h1);
                    *(uint32_t*)&d_hLo[off] = packbf2(l0, l1);
                }
            }
        }
    }
}

// ================= K2: hL = h@WL^T (bf16), hR = h@WR^T + bL (f32) =================
// smem: A (2 ch x hi/lo, 4x16K = 64K at 0), W (same, 64K at 65536)
#define K2_SMEM 131072

__global__ __launch_bounds__(256)
void combine_mma_kernel(const float* __restrict__ WL, const float* __restrict__ WR,
                        const float* __restrict__ bL)
{
    extern __shared__ char smem[];
    const uint32_t sb = smem_u32(smem);
    const int tid  = threadIdx.x;
    const int lane = tid & 31;
    const int wid  = tid >> 5;
    const int wm   = wid & 1;
    const int wn   = wid >> 1;
    const int row0 = blockIdx.x * 128;

    // A tiles: bf16 hi/lo straight from global (pre-split by K1)
    #pragma unroll
    for (int ch = 0; ch < 2; ch++) {
        #pragma unroll
        for (int hl = 0; hl < 2; hl++) {
            const __nv_bfloat16* A = hl ? d_hLo : d_hHi;
            char* t = smem + (ch * 2 + hl) * 16384;
            #pragma unroll
            for (int it = 0; it < 4; it++) {
                int e = tid + it * 256;
                int r = e >> 3, g = e & 7;
                uint4 v = make_uint4(0, 0, 0, 0);
                int gm = row0 + r;
                if (gm < NN) v = *(const uint4*)&A[(size_t)gm * HID + ch * 64 + g * 8];
                uint32_t sw = SWZ128((uint32_t)(r * 128 + g * 16));
                *(uint4*)(t + sw) = v;
            }
        }
    }

    #pragma unroll 1
    for (int pass = 0; pass < 2; pass++) {
        const float* W = pass ? WR : WL;
        // load W (fp32 -> hi/lo) into W area
        #pragma unroll
        for (int ch = 0; ch < 2; ch++) {
            char* thi = smem + 65536 + (ch * 2) * 16384;
            char* tlo = thi + 16384;
            #pragma unroll
            for (int it = 0; it < 8; it++) {
                int e = tid + it * 256;
                int r = e >> 4, c4 = (e & 15) << 2;
                float4 v = *(const float4*)&W[(size_t)r * HID + ch * 64 + c4];
                uint2 hi, lo; split4(v, hi, lo);
                uint32_t sw = SWZ128((uint32_t)(r * 128 + c4 * 2));
                *(uint2*)(thi + sw) = hi;
                *(uint2*)(tlo + sw) = lo;
            }
        }
        __syncthreads();

        float acc[4][4][4];
        #pragma unroll
        for (int i = 0; i < 4; i++)
            #pragma unroll
            for (int j = 0; j < 4; j++)
                #pragma unroll
                for (int q = 0; q < 4; q++) acc[i][j][q] = 0.f;

        #pragma unroll
        for (int ks8 = 0; ks8 < 8; ks8++) {
            const int ch = ks8 >> 2, ks = ks8 & 3;
            const uint32_t aHi = sb + (ch * 2) * 16384, aLo = aHi + 16384;
            const uint32_t wHi = sb + 65536 + (ch * 2) * 16384, wLo = wHi + 16384;
            uint32_t ahi[4][4], alo[4][4];
            #pragma unroll
            for (int mi = 0; mi < 4; mi++) {
                LDSM_X4(ahi[mi], addrA(aHi, wm * 4 + mi, ks, lane));
                LDSM_X4(alo[mi], addrA(aLo, wm * 4 + mi, ks, lane));
            }
            #pragma unroll
            for (int ni = 0; ni < 4; ni++) {
                uint32_t bh[2], bl[2];
                LDSM_X2(bh, addrB(wHi, wn * 4 + ni, ks, lane));
                LDSM_X2(bl, addrB(wLo, wn * 4 + ni, ks, lane));
                #pragma unroll
                for (int mi = 0; mi < 4; mi++) {
                    MMA_BF16(acc[mi][ni], ahi[mi], bh);
                    MMA_BF16(acc[mi][ni], ahi[mi], bl);
                    MMA_BF16(acc[mi][ni], alo[mi], bh);
                }
            }
        }

        // epilogue
        #pragma unroll
        for (int ni = 0; ni < 4; ni++) {
            int cc = wn * 32 + ni * 8 + (lane & 3) * 2;
            float b0 = pass ? bL[cc] : 0.f, b1 = pass ? bL[cc + 1] : 0.f;
            #pragma unroll
            for (int mi = 0; mi < 4; mi++) {
                int r0 = row0 + wm * 64 + mi * 16 + (lane >> 2);
                #pragma unroll
                for (int half = 0; half < 2; half++) {
                    int r = r0 + half * 8;
                    if (r < NN) {
                        size_t off = (size_t)r * HID + cc;
                        float v0 = acc[mi][ni][half * 2 + 0] + b0;
                        float v1 = acc[mi][ni][half * 2 + 1] + b1;
                        if (pass == 0) {
                            *(uint32_t*)&d_hLb[off] =
                                packbf2(__float2bfloat16(v0), __float2bfloat16(v1));
                        } else {
                            *(float2*)&d_hR[off] = make_float2(v0, v1);
                        }
                    }
                }
            }
        }
        __syncthreads();   // before overwriting W area (pass 0 -> 1)
    }
}

// ================= K3: bucket edges by dst =================
__global__ void edge_bucket_kernel(const int* __restrict__ ei) {
    int i = blockIdx.x * blockDim.x + threadIdx.x;
    if (i >= NEDGE) return;
    int src = ei[i];
    int dst = ei[NEDGE + i];
    if ((unsigned)src >= NN || (unsigned)dst >= NN) return;
    int pos = atomicAdd(&d_cnt[dst], 1);
    if (pos < CAP) d_slot[(size_t)dst * CAP + pos] = src;
}

// ================= K4: gather (bf16 hL) + combine + LN + relu + pool =================
__global__ __launch_bounds__(256)
void gather_ln_pool_kernel(const float* __restrict__ lng,
                           const float* __restrict__ lnb)
{
    const int lane   = threadIdx.x & 31;
    const int warp   = threadIdx.x >> 5;
    const int nwarps = blockDim.x >> 5;

    const float4* HR4 = (const float4*)d_hR;
    const float4  g4  = ((const float4*)lng)[lane];
    const float4  b4  = ((const float4*)lnb)[lane];

    float4 pacc = make_float4(0.f, 0.f, 0.f, 0.f);

    for (int node = blockIdx.x * nwarps + warp; node < NN;
         node += gridDim.x * nwarps)
    {
        int deg = d_cnt[node];
        int dn  = min(deg, CAP);

        float4 acc = make_float4(0.f, 0.f, 0.f, 0.f);
        for (int base = 0; base < dn; base += 32) {
            int myslot = 0;
            if (base + lane < dn) myslot = d_slot[(size_t)node * CAP + base + lane];
            int m = min(32, dn - base);
            for (int j = 0; j < m; j++) {
                int s = __shfl_sync(0xffffffffu, myslot, j);
                uint2 p = *(const uint2*)&d_hLb[(size_t)s * HID + lane * 4];
                float2 f0 = __bfloat1622float2(*(__nv_bfloat162*)&p.x);
                float2 f1 = __bfloat1622float2(*(__nv_bfloat162*)&p.y);
                acc.x += f0.x; acc.y += f0.y; acc.z += f1.x; acc.w += f1.y;
            }
        }

        float inv = 1.f / fmaxf((float)deg, 1.f);
        float4 hr = HR4[(size_t)node * 32 + lane];
        float4 y;
        y.x = fmaf(acc.x, inv, hr.x);
        y.y = fmaf(acc.y, inv, hr.y);
        y.z = fmaf(acc.z, inv, hr.z);
        y.w = fmaf(acc.w, inv, hr.w);

        float s1 = y.x + y.y + y.z + y.w;
        float s2 = y.x * y.x + y.y * y.y + y.z * y.z + y.w * y.w;
        #pragma unroll
        for (int o = 16; o > 0; o >>= 1) {
            s1 += __shfl_xor_sync(0xffffffffu, s1, o);
            s2 += __shfl_xor_sync(0xffffffffu, s2, o);
        }
        float mu   = s1 * (1.f / 128.f);
        float var  = s2 * (1.f / 128.f) - mu * mu;
        float rstd = rsqrtf(var + 1e-5f);

        pacc.x += fmaxf((y.x - mu) * rstd * g4.x + b4.x, 0.f);
        pacc.y += fmaxf((y.y - mu) * rstd * g4.y + b4.y, 0.f);
        pacc.z += fmaxf((y.z - mu) * rstd * g4.z + b4.z, 0.f);
        pacc.w += fmaxf((y.w - mu) * rstd * g4.w + b4.w, 0.f);
    }

    __shared__ float sp[8][128];
    ((float4*)sp[warp])[lane] = pacc;
    __syncthreads();
    int t = threadIdx.x;
    if (t < HID) {
        float s = 0.f;
        #pragma unroll
        for (int w = 0; w < 8; w++) s += sp[w][t];
        atomicAdd(&d_pool[t], s);
    }
}

// ================= K5: final linear =================
__global__ void final_kernel(const float* __restrict__ ow,
                             const float* __restrict__ ob,
                             float* __restrict__ out)
{
    __shared__ float g[128];
    int t = threadIdx.x;
    g[t] = d_pool[t] * (1.f / (float)NN);
    __syncthreads();
    float s = ob[t];
    #pragma unroll 8
    for (int f = 0; f < 128; f++)
        s = fmaf(g[f], ow[(size_t)t * 128 + f], s);
    out[t] = s;
}

// ================= launch =================
extern "C" void kernel_launch(void* const* d_in, const int* in_sizes, int n_in,
                              void* d_out, int out_size)
{
    const float* x       = (const float*)d_in[0];
    const int*   ei      = (const int*)d_in[1];
    const float* proj_w  = (const float*)d_in[2];
    const float* proj_b  = (const float*)d_in[3];
    const float* lin_l_w = (const float*)d_in[4];
    const float* lin_l_b = (const float*)d_in[5];
    const float* lin_r_w = (const float*)d_in[6];
    const float* ln_g    = (const float*)d_in[7];
    const float* ln_b    = (const float*)d_in[8];
    const float* out_w   = (const float*)d_in[9];
    const float* out_b   = (const float*)d_in[10];
    float* out = (float*)d_out;

    static bool attr_done = false;
    if (!attr_done) {
        cudaFuncSetAttribute(proj_mma_kernel,    cudaFuncAttributeMaxDynamicSharedMemorySize, K1_SMEM);
        cudaFuncSetAttribute(combine_mma_kernel, cudaFuncAttributeMaxDynamicSharedMemorySize, K2_SMEM);
        attr_done = true;
    }

    const int gblocks = (NN + 127) / 128;   // 391

    zero_kernel<<<(NN + 255) / 256, 256>>>();
    proj_mma_kernel<<<gblocks, 256, K1_SMEM>>>(x, proj_w, proj_b);
    combine_mma_kernel<<<gblocks, 256, K2_SMEM>>>(lin_l_w, lin_r_w, lin_l_b);
    edge_bucket_kernel<<<(NEDGE + 255) / 256, 256>>>(ei);
    gather_ln_pool_kernel<<<592, 256>>>(ln_g, ln_b);
    final_kernel<<<1, 128>>>(out_w, out_b, out);
}

// round 6
// speedup vs baseline: 2.2210x; 1.4921x over previous
#include <cuda_runtime.h>
#include <cuda_bf16.h>
#include <stdint.h>

#define NN    50000
#define NEDGE 1600000
#define NDIM  1024
#define HID   128
#define CAP   128
#define NBLK  391   // ceil(NN/128)

// ================= scratch =================
// pre-split weights, swizzled tile layout (bf16)
__device__ uint8_t d_pwT[16][2][16384];          // proj_w  [ch][hl][tile]
__device__ uint8_t d_wT [2][2][2][16384];        // [w L/R][hl][ch][tile]
// h in swizzled tile layout: [block][hl][ch][tile]
__device__ uint8_t d_hT [NBLK][2][2][16384];
__device__ __nv_bfloat16 d_hLb[(size_t)NN * HID];  // hL bf16 (gather operand)
__device__ float         d_hR [(size_t)NN * HID];  // h @ lin_r_w.T + lin_l_b
__device__ int           d_cnt[NN];
__device__ int           d_slot[(size_t)NN * CAP];
__device__ float         d_pool[HID];

// ================= helpers =================
__device__ __forceinline__ uint32_t smem_u32(const void* p) {
    uint32_t a;
    asm("{ .reg .u64 t; cvta.to.shared.u64 t, %1; cvt.u32.u64 %0, t; }" : "=r"(a) : "l"(p));
    return a;
}
#define SWZ128(o) ((o) ^ (((o) >> 3) & 0x70))

__device__ __forceinline__ uint32_t packbf2(__nv_bfloat16 a, __nv_bfloat16 b) {
    return (uint32_t)__bfloat16_as_ushort(a) | ((uint32_t)__bfloat16_as_ushort(b) << 16);
}
__device__ __forceinline__ void split4(float4 v, uint2& hi, uint2& lo) {
    __nv_bfloat16 hx = __float2bfloat16(v.x), hy = __float2bfloat16(v.y);
    __nv_bfloat16 hz = __float2bfloat16(v.z), hw = __float2bfloat16(v.w);
    __nv_bfloat16 lx = __float2bfloat16(v.x - __bfloat162float(hx));
    __nv_bfloat16 ly = __float2bfloat16(v.y - __bfloat162float(hy));
    __nv_bfloat16 lz = __float2bfloat16(v.z - __bfloat162float(hz));
    __nv_bfloat16 lw = __float2bfloat16(v.w - __bfloat162float(hw));
    hi.x = packbf2(hx, hy); hi.y = packbf2(hz, hw);
    lo.x = packbf2(lx, ly); lo.y = packbf2(lz, lw);
}

#define LDSM_X4(r, a) \
    asm volatile("ldmatrix.sync.aligned.m8n8.x4.shared.b16 {%0,%1,%2,%3}, [%4];" \
        : "=r"((r)[0]), "=r"((r)[1]), "=r"((r)[2]), "=r"((r)[3]) : "r"(a))
#define LDSM_X2(r, a) \
    asm volatile("ldmatrix.sync.aligned.m8n8.x2.shared.b16 {%0,%1}, [%2];" \
        : "=r"((r)[0]), "=r"((r)[1]) : "r"(a))
#define MMA_BF16(d, a, b) \
    asm volatile("mma.sync.aligned.m16n8k16.row.col.f32.bf16.bf16.f32 " \
        "{%0,%1,%2,%3}, {%4,%5,%6,%7}, {%8,%9}, {%0,%1,%2,%3};" \
        : "+f"((d)[0]), "+f"((d)[1]), "+f"((d)[2]), "+f"((d)[3]) \
        : "r"((a)[0]), "r"((a)[1]), "r"((a)[2]), "r"((a)[3]), "r"((b)[0]), "r"((b)[1]))

#define CP_A16(dst, src) \
    asm volatile("cp.async.cg.shared.global [%0], [%1], 16;" :: "r"(dst), "l"(src))
#define CP_COMMIT() asm volatile("cp.async.commit_group;")
#define CP_WAIT0()  asm volatile("cp.async.wait_group 0;" ::: "memory")
#define CP_WAIT1()  asm volatile("cp.async.wait_group 1;" ::: "memory")

// A-frag ldmatrix address: tile [128 rows][64 bf16], row stride 128B, SW128
__device__ __forceinline__ uint32_t addrA(uint32_t base, int mi, int ks, int lane) {
    int row  = mi * 16 + (lane & 15);
    int kb   = ks * 32 + ((lane >> 4) << 4);
    return base + SWZ128((uint32_t)(row * 128 + kb));
}
// B-frag address (non-trans): W tile [128 n][64 k]
__device__ __forceinline__ uint32_t addrB(uint32_t base, int ni, int ks, int lane) {
    int row = ni * 8 + (lane & 7);
    int kb  = ks * 32 + (((lane >> 3) & 1) << 4);
    return base + SWZ128((uint32_t)(row * 128 + kb));
}

// ================= K0 =================
__global__ void zero_kernel() {
    int i = blockIdx.x * blockDim.x + threadIdx.x;
    if (i < NN)  d_cnt[i] = 0;
    if (i < HID) d_pool[i] = 0.f;
}

// ================= Kp: pre-split weights into swizzled bf16 tiles =================
// float4 elems: proj 32768, wl 4096, wr 4096
__global__ void presplit_kernel(const float* __restrict__ pw,
                                const float* __restrict__ wl,
                                const float* __restrict__ wr)
{
    int i = blockIdx.x * blockDim.x + threadIdx.x;
    if (i < 32768) {
        int n  = i >> 8;             // row (0..127), 256 float4 per row
        int k4 = (i & 255) << 2;     // k col (0..1020)
        int ch = k4 >> 6, kk = k4 & 63;
        float4 v = ((const float4*)pw)[i];
        uint2 hi, lo; split4(v, hi, lo);
        uint32_t sw = SWZ128((uint32_t)(n * 128 + kk * 2));
        *(uint2*)&d_pwT[ch][0][sw] = hi;
        *(uint2*)&d_pwT[ch][1][sw] = lo;
    } else if (i < 40960) {
        int j = i - 32768;
        int w = j >= 4096;
        if (w) j -= 4096;
        const float* W = w ? wr : wl;
        int n  = j >> 5;             // 32 float4 per row
        int k4 = (j & 31) << 2;
        int ch = k4 >> 6, kk = k4 & 63;
        float4 v = ((const float4*)W)[j];
        uint2 hi, lo; split4(v, hi, lo);
        uint32_t sw = SWZ128((uint32_t)(n * 128 + kk * 2));
        *(uint2*)&d_wT[w][0][ch][sw] = hi;
        *(uint2*)&d_wT[w][1][ch][sw] = lo;
    }
}

// ================= K1: h = relu(x @ proj_w.T + b), pipelined =================
// smem: Ahi 0, Alo 16K; W stage s at 32768 + s*32768 (hi, lo 16K each)
#define K1_SMEM (32768 + 2 * 32768)

__global__ __launch_bounds__(256)
void proj_mma_kernel(const float* __restrict__ X, const float* __restrict__ bias)
{
    extern __shared__ char smem[];
    const uint32_t sb = smem_u32(smem);
    const int tid  = threadIdx.x;
    const int lane = tid & 31;
    const int wid  = tid >> 5;
    const int wm   = wid & 1;
    const int wn   = wid >> 1;
    const int row0 = blockIdx.x * 128;

    float acc[4][4][4];
    #pragma unroll
    for (int i = 0; i < 4; i++)
        #pragma unroll
        for (int j = 0; j < 4; j++)
            #pragma unroll
            for (int q = 0; q < 4; q++) acc[i][j][q] = 0.f;

    const uint32_t aHi = sb, aLo = sb + 16384;

    float4 xv[8];
    // preload X chunk 0 into regs
    #pragma unroll
    for (int it = 0; it < 8; it++) {
        int e = tid + it * 256;
        int r = e >> 4, c4 = (e & 15) << 2;
        int gm = row0 + r;
        xv[it] = (gm < NN) ? *(const float4*)&X[(size_t)gm * NDIM + c4]
                           : make_float4(0.f, 0.f, 0.f, 0.f);
    }
    // cp.async W chunk 0 -> stage 0
    {
        uint32_t wst = sb + 32768;
        #pragma unroll
        for (int q = 0; q < 4; q++) {
            CP_A16(wst + tid * 16 + q * 4096,         &d_pwT[0][0][tid * 16 + q * 4096]);
            CP_A16(wst + 16384 + tid * 16 + q * 4096, &d_pwT[0][1][tid * 16 + q * 4096]);
        }
        CP_COMMIT();
    }

    #pragma unroll 1
    for (int c = 0; c < 16; c++) {
        const int s = c & 1;
        // convert & store X regs -> A smem
        #pragma unroll
        for (int it = 0; it < 8; it++) {
            int e = tid + it * 256;
            int r = e >> 4, c4 = (e & 15) << 2;
            uint2 hi, lo; split4(xv[it], hi, lo);
            uint32_t sw = SWZ128((uint32_t)(r * 128 + c4 * 2));
            *(uint2*)(smem + sw)         = hi;
            *(uint2*)(smem + 16384 + sw) = lo;
        }
        // prefetch W chunk c+1
        if (c < 15) {
            uint32_t wst = sb + 32768 + (s ^ 1) * 32768;
            #pragma unroll
            for (int q = 0; q < 4; q++) {
                CP_A16(wst + tid * 16 + q * 4096,         &d_pwT[c + 1][0][tid * 16 + q * 4096]);
                CP_A16(wst + 16384 + tid * 16 + q * 4096, &d_pwT[c + 1][1][tid * 16 + q * 4096]);
            }
            CP_COMMIT();
            CP_WAIT1();
        } else {
            CP_WAIT0();
        }
        __syncthreads();

        // issue X loads for chunk c+1 (consumed next iter; overlaps MMAs)
        if (c < 15) {
            const int kc = (c + 1) * 64;
            #pragma unroll
            for (int it = 0; it < 8; it++) {
                int e = tid + it * 256;
                int r = e >> 4, c4 = (e & 15) << 2;
                int gm = row0 + r;
                xv[it] = (gm < NN) ? *(const float4*)&X[(size_t)gm * NDIM + kc + c4]
                                   : make_float4(0.f, 0.f, 0.f, 0.f);
            }
        }

        const uint32_t bHi = sb + 32768 + s * 32768, bLo = bHi + 16384;
        #pragma unroll
        for (int ks = 0; ks < 4; ks++) {
            uint32_t ahi[4][4], alo[4][4];
            #pragma unroll
            for (int mi = 0; mi < 4; mi++) {
                LDSM_X4(ahi[mi], addrA(aHi, wm * 4 + mi, ks, lane));
                LDSM_X4(alo[mi], addrA(aLo, wm * 4 + mi, ks, lane));
            }
            #pragma unroll
            for (int ni = 0; ni < 4; ni++) {
                uint32_t bh[2], bl[2];
                LDSM_X2(bh, addrB(bHi, wn * 4 + ni, ks, lane));
                LDSM_X2(bl, addrB(bLo, wn * 4 + ni, ks, lane));
                #pragma unroll
                for (int mi = 0; mi < 4; mi++) {
                    MMA_BF16(acc[mi][ni], ahi[mi], bh);
                    MMA_BF16(acc[mi][ni], ahi[mi], bl);
                    MMA_BF16(acc[mi][ni], alo[mi], bh);
                }
            }
        }
        __syncthreads();
    }

    // epilogue: +bias, relu, split, write swizzled tile-format h
    uint8_t* hT = &d_hT[blockIdx.x][0][0][0];
    #pragma unroll
    for (int ni = 0; ni < 4; ni++) {
        int cc = wn * 32 + ni * 8 + (lane & 3) * 2;
        int ch = cc >> 6, kk = cc & 63;
        float b0 = bias[cc], b1 = bias[cc + 1];
        #pragma unroll
        for (int mi = 0; mi < 4; mi++) {
            int rl0 = wm * 64 + mi * 16 + (lane >> 2);
            #pragma unroll
            for (int half = 0; half < 2; half++) {
                int rl = rl0 + half * 8;
                if (row0 + rl < NN) {
                    float v0 = fmaxf(acc[mi][ni][half * 2 + 0] + b0, 0.f);
                    float v1 = fmaxf(acc[mi][ni][half * 2 + 1] + b1, 0.f);
                    __nv_bfloat16 h0 = __float2bfloat16(v0), h1 = __float2bfloat16(v1);
                    __nv_bfloat16 l0 = __float2bfloat16(v0 - __bfloat162float(h0));
                    __nv_bfloat16 l1 = __float2bfloat16(v1 - __bfloat162float(h1));
                    uint32_t sw = SWZ128((uint32_t)(rl * 128 + kk * 2));
                    *(uint32_t*)(hT + ch * 16384 + sw)         = packbf2(h0, h1);
                    *(uint32_t*)(hT + 32768 + ch * 16384 + sw) = packbf2(l0, l1);
                }
            }
        }
    }
}

// ================= K2: hL = h@WL^T (bf16), hR = h@WR^T + bL (f32) =================
// smem: h 64K at 0 ([hl][ch] tiles), WL 64K at 65536, WR 64K at 131072
#define K2_SMEM 196608

__global__ __launch_bounds__(256)
void combine_mma_kernel(const float* __restrict__ bL)
{
    extern __shared__ char smem[];
    const uint32_t sb = smem_u32(smem);
    const int tid  = threadIdx.x;
    const int lane = tid & 31;
    const int wid  = tid >> 5;
    const int wm   = wid & 1;
    const int wn   = wid >> 1;
    const int row0 = blockIdx.x * 128;

    // cp.async everything: h (64KB), WL (64KB), WR (64KB)
    const uint8_t* hsrc = &d_hT[blockIdx.x][0][0][0];
    const uint8_t* wsrc = &d_wT[0][0][0][0];
    #pragma unroll
    for (int q = 0; q < 16; q++)
        CP_A16(sb + tid * 16 + q * 4096, hsrc + tid * 16 + q * 4096);
    #pragma unroll
    for (int q = 0; q < 32; q++)
        CP_A16(sb + 65536 + tid * 16 + q * 4096, wsrc + tid * 16 + q * 4096);
    CP_COMMIT();
    CP_WAIT0();
    __syncthreads();

    #pragma unroll 1
    for (int pass = 0; pass < 2; pass++) {
        float acc[4][4][4];
        #pragma unroll
        for (int i = 0; i < 4; i++)
            #pragma unroll
            for (int j = 0; j < 4; j++)
                #pragma unroll
                for (int q = 0; q < 4; q++) acc[i][j][q] = 0.f;

        const uint32_t wbase = sb + 65536 + pass * 65536;
        #pragma unroll
        for (int ks8 = 0; ks8 < 8; ks8++) {
            const int ch = ks8 >> 2, ks = ks8 & 3;
            const uint32_t aHi = sb + ch * 16384,          aLo = sb + 32768 + ch * 16384;
            const uint32_t wHi = wbase + ch * 16384,       wLo = wbase + 32768 + ch * 16384;
            uint32_t ahi[4][4], alo[4][4];
            #pragma unroll
            for (int mi = 0; mi < 4; mi++) {
                LDSM_X4(ahi[mi], addrA(aHi, wm * 4 + mi, ks, lane));
                LDSM_X4(alo[mi], addrA(aLo, wm * 4 + mi, ks, lane));
            }
            #pragma unroll
            for (int ni = 0; ni < 4; ni++) {
                uint32_t bh[2], bl[2];
                LDSM_X2(bh, addrB(wHi, wn * 4 + ni, ks, lane));
                LDSM_X2(bl, addrB(wLo, wn * 4 + ni, ks, lane));
                #pragma unroll
                for (int mi = 0; mi < 4; mi++) {
                    MMA_BF16(acc[mi][ni], ahi[mi], bh);
                    MMA_BF16(acc[mi][ni], ahi[mi], bl);
                    MMA_BF16(acc[mi][ni], alo[mi], bh);
                }
            }
        }

        #pragma unroll
        for (int ni = 0; ni < 4; ni++) {
            int cc = wn * 32 + ni * 8 + (lane & 3) * 2;
            float b0 = pass ? bL[cc] : 0.f, b1 = pass ? bL[cc + 1] : 0.f;
            #pragma unroll
            for (int mi = 0; mi < 4; mi++) {
                int r0 = row0 + wm * 64 + mi * 16 + (lane >> 2);
                #pragma unroll
                for (int half = 0; half < 2; half++) {
                    int r = r0 + half * 8;
                    if (r < NN) {
                        size_t off = (size_t)r * HID + cc;
                        float v0 = acc[mi][ni][half * 2 + 0] + b0;
                        float v1 = acc[mi][ni][half * 2 + 1] + b1;
                        if (pass == 0) {
                            *(uint32_t*)&d_hLb[off] =
                                packbf2(__float2bfloat16(v0), __float2bfloat16(v1));
                        } else {
                            *(float2*)&d_hR[off] = make_float2(v0, v1);
                        }
                    }
                }
            }
        }
    }
}

// ================= K3: bucket edges by dst =================
__global__ void edge_bucket_kernel(const int* __restrict__ ei) {
    int i = blockIdx.x * blockDim.x + threadIdx.x;
    if (i >= NEDGE) return;
    int src = ei[i];
    int dst = ei[NEDGE + i];
    if ((unsigned)src >= NN || (unsigned)dst >= NN) return;
    int pos = atomicAdd(&d_cnt[dst], 1);
    if (pos < CAP) d_slot[(size_t)dst * CAP + pos] = src;
}

// ================= K4: gather (bf16 hL) + combine + LN + relu + pool =================
__global__ __launch_bounds__(256)
void gather_ln_pool_kernel(const float* __restrict__ lng,
                           const float* __restrict__ lnb)
{
    const int lane   = threadIdx.x & 31;
    const int warp   = threadIdx.x >> 5;
    const int nwarps = blockDim.x >> 5;

    const float4* HR4 = (const float4*)d_hR;
    const float4  g4  = ((const float4*)lng)[lane];
    const float4  b4  = ((const float4*)lnb)[lane];

    float4 pacc = make_float4(0.f, 0.f, 0.f, 0.f);

    for (int node = blockIdx.x * nwarps + warp; node < NN;
         node += gridDim.x * nwarps)
    {
        int deg = d_cnt[node];
        int dn  = min(deg, CAP);

        float4 acc = make_float4(0.f, 0.f, 0.f, 0.f);
        for (int base = 0; base < dn; base += 32) {
            int myslot = 0;
            if (base + lane < dn) myslot = d_slot[(size_t)node * CAP + base + lane];
            int m = min(32, dn - base);
            for (int j = 0; j < m; j++) {
                int s = __shfl_sync(0xffffffffu, myslot, j);
                uint2 p = *(const uint2*)&d_hLb[(size_t)s * HID + lane * 4];
                float2 f0 = __bfloat1622float2(*(__nv_bfloat162*)&p.x);
                float2 f1 = __bfloat1622float2(*(__nv_bfloat162*)&p.y);
                acc.x += f0.x; acc.y += f0.y; acc.z += f1.x; acc.w += f1.y;
            }
        }

        float inv = 1.f / fmaxf((float)deg, 1.f);
        float4 hr = HR4[(size_t)node * 32 + lane];
        float4 y;
        y.x = fmaf(acc.x, inv, hr.x);
        y.y = fmaf(acc.y, inv, hr.y);
        y.z = fmaf(acc.z, inv, hr.z);
        y.w = fmaf(acc.w, inv, hr.w);

        float s1 = y.x + y.y + y.z + y.w;
        float s2 = y.x * y.x + y.y * y.y + y.z * y.z + y.w * y.w;
        #pragma unroll
        for (int o = 16; o > 0; o >>= 1) {
            s1 += __shfl_xor_sync(0xffffffffu, s1, o);
            s2 += __shfl_xor_sync(0xffffffffu, s2, o);
        }
        float mu   = s1 * (1.f / 128.f);
        float var  = s2 * (1.f / 128.f) - mu * mu;
        float rstd = rsqrtf(var + 1e-5f);

        pacc.x += fmaxf((y.x - mu) * rstd * g4.x + b4.x, 0.f);
        pacc.y += fmaxf((y.y - mu) * rstd * g4.y + b4.y, 0.f);
        pacc.z += fmaxf((y.z - mu) * rstd * g4.z + b4.z, 0.f);
        pacc.w += fmaxf((y.w - mu) * rstd * g4.w + b4.w, 0.f);
    }

    __shared__ float sp[8][128];
    ((float4*)sp[warp])[lane] = pacc;
    __syncthreads();
    int t = threadIdx.x;
    if (t < HID) {
        float s = 0.f;
        #pragma unroll
        for (int w = 0; w < 8; w++) s += sp[w][t];
        atomicAdd(&d_pool[t], s);
    }
}

// ================= K5: final linear =================
__global__ void final_kernel(const float* __restrict__ ow,
                             const float* __restrict__ ob,
                             float* __restrict__ out)
{
    __shared__ float g[128];
    int t = threadIdx.x;
    g[t] = d_pool[t] * (1.f / (float)NN);
    __syncthreads();
    float s = ob[t];
    #pragma unroll 8
    for (int f = 0; f < 128; f++)
        s = fmaf(g[f], ow[(size_t)t * 128 + f], s);
    out[t] = s;
}

// ================= launch =================
extern "C" void kernel_launch(void* const* d_in, const int* in_sizes, int n_in,
                              void* d_out, int out_size)
{
    const float* x       = (const float*)d_in[0];
    const int*   ei      = (const int*)d_in[1];
    const float* proj_w  = (const float*)d_in[2];
    const float* proj_b  = (const float*)d_in[3];
    const float* lin_l_w = (const float*)d_in[4];
    const float* lin_l_b = (const float*)d_in[5];
    const float* lin_r_w = (const float*)d_in[6];
    const float* ln_g    = (const float*)d_in[7];
    const float* ln_b    = (const float*)d_in[8];
    const float* out_w   = (const float*)d_in[9];
    const float* out_b   = (const float*)d_in[10];
    float* out = (float*)d_out;

    static bool attr_done = false;
    if (!attr_done) {
        cudaFuncSetAttribute(proj_mma_kernel,    cudaFuncAttributeMaxDynamicSharedMemorySize, K1_SMEM);
        cudaFuncSetAttribute(combine_mma_kernel, cudaFuncAttributeMaxDynamicSharedMemorySize, K2_SMEM);
        attr_done = true;
    }

    zero_kernel<<<(NN + 255) / 256, 256>>>();
    presplit_kernel<<<160, 256>>>(proj_w, lin_l_w, lin_r_w);
    proj_mma_kernel<<<NBLK, 256, K1_SMEM>>>(x, proj_b);
    combine_mma_kernel<<<NBLK, 256, K2_SMEM>>>(lin_l_b);
    edge_bucket_kernel<<<(NEDGE + 255) / 256, 256>>>(ei);
    gather_ln_pool_kernel<<<592, 256>>>(ln_g, ln_b);
    final_kernel<<<1, 128>>>(out_w, out_b, out);
}

// round 7
// speedup vs baseline: 2.6151x; 1.1774x over previous
#include <cuda_runtime.h>
#include <cuda_bf16.h>
#include <stdint.h>

#define NN    50000
#define NEDGE 1600000
#define NDIM  1024
#define HID   128
#define CAP   128
#define NBLK  391   // ceil(NN/128)

// ================= scratch =================
__device__ uint8_t d_pwT[16][2][16384];          // proj_w  [ch][hl][tile]
__device__ uint8_t d_wT [2][2][2][16384];        // [w L/R][hl][ch][tile]
__device__ uint8_t d_hT [NBLK][2][2][16384];     // h tiles [block][hl][ch]
__device__ __nv_bfloat16 d_hLb[(size_t)NN * HID];
__device__ float         d_hR [(size_t)NN * HID];
__device__ int           d_cnt[NN];
__device__ int           d_slot[(size_t)NN * CAP];
__device__ float         d_pool[HID];

// ================= helpers =================
__device__ __forceinline__ uint32_t smem_u32(const void* p) {
    uint32_t a;
    asm("{ .reg .u64 t; cvta.to.shared.u64 t, %1; cvt.u32.u64 %0, t; }" : "=r"(a) : "l"(p));
    return a;
}
#define SWZ128(o) ((o) ^ (((o) >> 3) & 0x70))

__device__ __forceinline__ uint32_t packbf2(__nv_bfloat16 a, __nv_bfloat16 b) {
    return (uint32_t)__bfloat16_as_ushort(a) | ((uint32_t)__bfloat16_as_ushort(b) << 16);
}
__device__ __forceinline__ void split4(float4 v, uint2& hi, uint2& lo) {
    __nv_bfloat16 hx = __float2bfloat16(v.x), hy = __float2bfloat16(v.y);
    __nv_bfloat16 hz = __float2bfloat16(v.z), hw = __float2bfloat16(v.w);
    __nv_bfloat16 lx = __float2bfloat16(v.x - __bfloat162float(hx));
    __nv_bfloat16 ly = __float2bfloat16(v.y - __bfloat162float(hy));
    __nv_bfloat16 lz = __float2bfloat16(v.z - __bfloat162float(hz));
    __nv_bfloat16 lw = __float2bfloat16(v.w - __bfloat162float(hw));
    hi.x = packbf2(hx, hy); hi.y = packbf2(hz, hw);
    lo.x = packbf2(lx, ly); lo.y = packbf2(lz, lw);
}

#define LDSM_X4(r, a) \
    asm volatile("ldmatrix.sync.aligned.m8n8.x4.shared.b16 {%0,%1,%2,%3}, [%4];" \
        : "=r"((r)[0]), "=r"((r)[1]), "=r"((r)[2]), "=r"((r)[3]) : "r"(a))
#define LDSM_X2(r, a) \
    asm volatile("ldmatrix.sync.aligned.m8n8.x2.shared.b16 {%0,%1}, [%2];" \
        : "=r"((r)[0]), "=r"((r)[1]) : "r"(a))
#define MMA_BF16(d, a, b) \
    asm volatile("mma.sync.aligned.m16n8k16.row.col.f32.bf16.bf16.f32 " \
        "{%0,%1,%2,%3}, {%4,%5,%6,%7}, {%8,%9}, {%0,%1,%2,%3};" \
        : "+f"((d)[0]), "+f"((d)[1]), "+f"((d)[2]), "+f"((d)[3]) \
        : "r"((a)[0]), "r"((a)[1]), "r"((a)[2]), "r"((a)[3]), "r"((b)[0]), "r"((b)[1]))

#define CP_A16(dst, src) \
    asm volatile("cp.async.cg.shared.global [%0], [%1], 16;" :: "r"(dst), "l"(src))
#define CP_COMMIT() asm volatile("cp.async.commit_group;")
#define CP_WAIT0()  asm volatile("cp.async.wait_group 0;" ::: "memory")
#define CP_WAIT1()  asm volatile("cp.async.wait_group 1;" ::: "memory")

// A-frag: tile [128 rows][64 bf16], row stride 128B, SW128; MI in 16-row units
__device__ __forceinline__ uint32_t addrA(uint32_t base, int MI, int ks, int lane) {
    int row  = MI * 16 + (lane & 15);
    int kb   = ks * 32 + ((lane >> 4) << 4);
    return base + SWZ128((uint32_t)(row * 128 + kb));
}
// B-frag (non-trans): W tile [128 n][64 k]; NI in 8-row units
__device__ __forceinline__ uint32_t addrB(uint32_t base, int NI, int ks, int lane) {
    int row = NI * 8 + (lane & 7);
    int kb  = ks * 32 + (((lane >> 3) & 1) << 4);
    return base + SWZ128((uint32_t)(row * 128 + kb));
}

// ================= K0 =================
__global__ void zero_kernel() {
    int i = blockIdx.x * blockDim.x + threadIdx.x;
    if (i < NN)  d_cnt[i] = 0;
    if (i < HID) d_pool[i] = 0.f;
}

// ================= Kp: pre-split weights =================
__global__ void presplit_kernel(const float* __restrict__ pw,
                                const float* __restrict__ wl,
                                const float* __restrict__ wr)
{
    int i = blockIdx.x * blockDim.x + threadIdx.x;
    if (i < 32768) {
        int n  = i >> 8;
        int k4 = (i & 255) << 2;
        int ch = k4 >> 6, kk = k4 & 63;
        float4 v = ((const float4*)pw)[i];
        uint2 hi, lo; split4(v, hi, lo);
        uint32_t sw = SWZ128((uint32_t)(n * 128 + kk * 2));
        *(uint2*)&d_pwT[ch][0][sw] = hi;
        *(uint2*)&d_pwT[ch][1][sw] = lo;
    } else if (i < 40960) {
        int j = i - 32768;
        int w = j >= 4096;
        if (w) j -= 4096;
        const float* W = w ? wr : wl;
        int n  = j >> 5;
        int k4 = (j & 31) << 2;
        int ch = k4 >> 6, kk = k4 & 63;
        float4 v = ((const float4*)W)[j];
        uint2 hi, lo; split4(v, hi, lo);
        uint32_t sw = SWZ128((uint32_t)(n * 128 + kk * 2));
        *(uint2*)&d_wT[w][0][ch][sw] = hi;
        *(uint2*)&d_wT[w][1][ch][sw] = lo;
    }
}

// ================= K1: h = relu(x @ proj_w.T + b), 512 threads =================
// smem: Ahi 0, Alo 16K; W stage s at 32768 + s*32768 (hi, lo 16K each)
#define K1_SMEM (32768 + 2 * 32768)

__global__ __launch_bounds__(512, 1)
void proj_mma_kernel(const float* __restrict__ X, const float* __restrict__ bias)
{
    extern __shared__ char smem[];
    const uint32_t sb = smem_u32(smem);
    const int tid  = threadIdx.x;
    const int lane = tid & 31;
    const int wid  = tid >> 5;        // 0..15
    const int wm   = wid & 3;         // 4 row groups of 32
    const int wn   = wid >> 2;        // 4 col groups of 32
    const int row0 = blockIdx.x * 128;

    float acc[2][4][4];
    #pragma unroll
    for (int i = 0; i < 2; i++)
        #pragma unroll
        for (int j = 0; j < 4; j++)
            #pragma unroll
            for (int q = 0; q < 4; q++) acc[i][j][q] = 0.f;

    const uint32_t aHi = sb, aLo = sb + 16384;

    float4 xv[4];
    #pragma unroll
    for (int it = 0; it < 4; it++) {
        int e = tid + it * 512;
        int r = e >> 4, c4 = (e & 15) << 2;
        int gm = row0 + r;
        xv[it] = (gm < NN) ? *(const float4*)&X[(size_t)gm * NDIM + c4]
                           : make_float4(0.f, 0.f, 0.f, 0.f);
    }
    {
        uint32_t wst = sb + 32768;
        #pragma unroll
        for (int q = 0; q < 2; q++) {
            CP_A16(wst + tid * 16 + q * 8192,         &d_pwT[0][0][tid * 16 + q * 8192]);
            CP_A16(wst + 16384 + tid * 16 + q * 8192, &d_pwT[0][1][tid * 16 + q * 8192]);
        }
        CP_COMMIT();
    }

    #pragma unroll 1
    for (int c = 0; c < 16; c++) {
        const int s = c & 1;
        #pragma unroll
        for (int it = 0; it < 4; it++) {
            int e = tid + it * 512;
            int r = e >> 4, c4 = (e & 15) << 2;
            uint2 hi, lo; split4(xv[it], hi, lo);
            uint32_t sw = SWZ128((uint32_t)(r * 128 + c4 * 2));
            *(uint2*)(smem + sw)         = hi;
            *(uint2*)(smem + 16384 + sw) = lo;
        }
        if (c < 15) {
            uint32_t wst = sb + 32768 + (s ^ 1) * 32768;
            #pragma unroll
            for (int q = 0; q < 2; q++) {
                CP_A16(wst + tid * 16 + q * 8192,         &d_pwT[c + 1][0][tid * 16 + q * 8192]);
                CP_A16(wst + 16384 + tid * 16 + q * 8192, &d_pwT[c + 1][1][tid * 16 + q * 8192]);
            }
            CP_COMMIT();
            CP_WAIT1();
        } else {
            CP_WAIT0();
        }
        __syncthreads();

        if (c < 15) {
            const int kc = (c + 1) * 64;
            #pragma unroll
            for (int it = 0; it < 4; it++) {
                int e = tid + it * 512;
                int r = e >> 4, c4 = (e & 15) << 2;
                int gm = row0 + r;
                xv[it] = (gm < NN) ? *(const float4*)&X[(size_t)gm * NDIM + kc + c4]
                                   : make_float4(0.f, 0.f, 0.f, 0.f);
            }
        }

        const uint32_t bHi = sb + 32768 + s * 32768, bLo = bHi + 16384;
        #pragma unroll
        for (int ks = 0; ks < 4; ks++) {
            uint32_t ahi[2][4], alo[2][4];
            #pragma unroll
            for (int mi = 0; mi < 2; mi++) {
                LDSM_X4(ahi[mi], addrA(aHi, wm * 2 + mi, ks, lane));
                LDSM_X4(alo[mi], addrA(aLo, wm * 2 + mi, ks, lane));
            }
            #pragma unroll
            for (int ni = 0; ni < 4; ni++) {
                uint32_t bh[2], bl[2];
                LDSM_X2(bh, addrB(bHi, wn * 4 + ni, ks, lane));
                LDSM_X2(bl, addrB(bLo, wn * 4 + ni, ks, lane));
                #pragma unroll
                for (int mi = 0; mi < 2; mi++) {
                    MMA_BF16(acc[mi][ni], ahi[mi], bh);
                    MMA_BF16(acc[mi][ni], ahi[mi], bl);
                    MMA_BF16(acc[mi][ni], alo[mi], bh);
                }
            }
        }
        __syncthreads();
    }

    // epilogue: +bias, relu, split, swizzled tile-format h
    uint8_t* hT = &d_hT[blockIdx.x][0][0][0];
    #pragma unroll
    for (int ni = 0; ni < 4; ni++) {
        int cc = wn * 32 + ni * 8 + (lane & 3) * 2;
        int ch = cc >> 6, kk = cc & 63;
        float b0 = bias[cc], b1 = bias[cc + 1];
        #pragma unroll
        for (int mi = 0; mi < 2; mi++) {
            int rl0 = wm * 32 + mi * 16 + (lane >> 2);
            #pragma unroll
            for (int half = 0; half < 2; half++) {
                int rl = rl0 + half * 8;
                if (row0 + rl < NN) {
                    float v0 = fmaxf(acc[mi][ni][half * 2 + 0] + b0, 0.f);
                    float v1 = fmaxf(acc[mi][ni][half * 2 + 1] + b1, 0.f);
                    __nv_bfloat16 h0 = __float2bfloat16(v0), h1 = __float2bfloat16(v1);
                    __nv_bfloat16 l0 = __float2bfloat16(v0 - __bfloat162float(h0));
                    __nv_bfloat16 l1 = __float2bfloat16(v1 - __bfloat162float(h1));
                    uint32_t sw = SWZ128((uint32_t)(rl * 128 + kk * 2));
                    *(uint32_t*)(hT + ch * 16384 + sw)         = packbf2(h0, h1);
                    *(uint32_t*)(hT + 32768 + ch * 16384 + sw) = packbf2(l0, l1);
                }
            }
        }
    }
}

// ================= K2: hL (bf16) and hR (f32), 512 threads =================
// smem: h 64K at 0, WL 64K at 65536, WR 64K at 131072
#define K2_SMEM 196608

__global__ __launch_bounds__(512, 1)
void combine_mma_kernel(const float* __restrict__ bL)
{
    extern __shared__ char smem[];
    const uint32_t sb = smem_u32(smem);
    const int tid  = threadIdx.x;
    const int lane = tid & 31;
    const int wid  = tid >> 5;
    const int wm   = wid & 3;
    const int wn   = wid >> 2;
    const int row0 = blockIdx.x * 128;

    const uint8_t* hsrc = &d_hT[blockIdx.x][0][0][0];
    const uint8_t* wsrc = &d_wT[0][0][0][0];
    #pragma unroll
    for (int q = 0; q < 8; q++)
        CP_A16(sb + tid * 16 + q * 8192, hsrc + tid * 16 + q * 8192);
    #pragma unroll
    for (int q = 0; q < 16; q++)
        CP_A16(sb + 65536 + tid * 16 + q * 8192, wsrc + tid * 16 + q * 8192);
    CP_COMMIT();
    CP_WAIT0();
    __syncthreads();

    #pragma unroll 1
    for (int pass = 0; pass < 2; pass++) {
        float acc[2][4][4];
        #pragma unroll
        for (int i = 0; i < 2; i++)
            #pragma unroll
            for (int j = 0; j < 4; j++)
                #pragma unroll
                for (int q = 0; q < 4; q++) acc[i][j][q] = 0.f;

        const uint32_t wbase = sb + 65536 + pass * 65536;
        #pragma unroll
        for (int ks8 = 0; ks8 < 8; ks8++) {
            const int ch = ks8 >> 2, ks = ks8 & 3;
            const uint32_t aHi = sb + ch * 16384,    aLo = sb + 32768 + ch * 16384;
            const uint32_t wHi = wbase + ch * 16384, wLo = wbase + 32768 + ch * 16384;
            uint32_t ahi[2][4], alo[2][4];
            #pragma unroll
            for (int mi = 0; mi < 2; mi++) {
                LDSM_X4(ahi[mi], addrA(aHi, wm * 2 + mi, ks, lane));
                LDSM_X4(alo[mi], addrA(aLo, wm * 2 + mi, ks, lane));
            }
            #pragma unroll
            for (int ni = 0; ni < 4; ni++) {
                uint32_t bh[2], bl[2];
                LDSM_X2(bh, addrB(wHi, wn * 4 + ni, ks, lane));
                LDSM_X2(bl, addrB(wLo, wn * 4 + ni, ks, lane));
                #pragma unroll
                for (int mi = 0; mi < 2; mi++) {
                    MMA_BF16(acc[mi][ni], ahi[mi], bh);
                    MMA_BF16(acc[mi][ni], ahi[mi], bl);
                    MMA_BF16(acc[mi][ni], alo[mi], bh);
                }
            }
        }

        #pragma unroll
        for (int ni = 0; ni < 4; ni++) {
            int cc = wn * 32 + ni * 8 + (lane & 3) * 2;
            float b0 = pass ? bL[cc] : 0.f, b1 = pass ? bL[cc + 1] : 0.f;
            #pragma unroll
            for (int mi = 0; mi < 2; mi++) {
                int r0 = row0 + wm * 32 + mi * 16 + (lane >> 2);
                #pragma unroll
                for (int half = 0; half < 2; half++) {
                    int r = r0 + half * 8;
                    if (r < NN) {
                        size_t off = (size_t)r * HID + cc;
                        float v0 = acc[mi][ni][half * 2 + 0] + b0;
                        float v1 = acc[mi][ni][half * 2 + 1] + b1;
                        if (pass == 0) {
                            *(uint32_t*)&d_hLb[off] =
                                packbf2(__float2bfloat16(v0), __float2bfloat16(v1));
                        } else {
                            *(float2*)&d_hR[off] = make_float2(v0, v1);
                        }
                    }
                }
            }
        }
    }
}

// ================= K3: bucket edges by dst =================
__global__ void edge_bucket_kernel(const int* __restrict__ ei) {
    int i = blockIdx.x * blockDim.x + threadIdx.x;
    if (i >= NEDGE) return;
    int src = ei[i];
    int dst = ei[NEDGE + i];
    if ((unsigned)src >= NN || (unsigned)dst >= NN) return;
    int pos = atomicAdd(&d_cnt[dst], 1);
    if (pos < CAP) d_slot[(size_t)dst * CAP + pos] = src;
}

// ================= K4: gather + combine + LN + relu + pool (MLP-4) =================
__global__ __launch_bounds__(256)
void gather_ln_pool_kernel(const float* __restrict__ lng,
                           const float* __restrict__ lnb)
{
    const int lane   = threadIdx.x & 31;
    const int warp   = threadIdx.x >> 5;
    const int nwarps = blockDim.x >> 5;

    const float4* HR4 = (const float4*)d_hR;
    const float4  g4  = ((const float4*)lng)[lane];
    const float4  b4  = ((const float4*)lnb)[lane];

    float4 pacc = make_float4(0.f, 0.f, 0.f, 0.f);

    for (int node = blockIdx.x * nwarps + warp; node < NN;
         node += gridDim.x * nwarps)
    {
        int deg = d_cnt[node];
        int dn  = min(deg, CAP);

        // preload slot list: lane holds slots {lane, lane+32, lane+64, lane+96}
        int sl[4];
        #pragma unroll
        for (int q = 0; q < 4; q++) {
            int idx = q * 32 + lane;
            sl[q] = (idx < dn) ? d_slot[(size_t)node * CAP + idx] : 0;
        }

        float4 a0 = make_float4(0.f, 0.f, 0.f, 0.f);
        float4 a1 = make_float4(0.f, 0.f, 0.f, 0.f);
        float4 a2 = make_float4(0.f, 0.f, 0.f, 0.f);
        float4 a3 = make_float4(0.f, 0.f, 0.f, 0.f);

        #pragma unroll
        for (int q = 0; q < 4; q++) {
            int base = q * 32;
            if (base >= dn) break;
            int cnt = min(32, dn - base);
            int my  = sl[q];
            int j = 0;
            #pragma unroll 2
            for (; j + 4 <= cnt; j += 4) {
                int s0 = __shfl_sync(0xffffffffu, my, j + 0);
                int s1 = __shfl_sync(0xffffffffu, my, j + 1);
                int s2 = __shfl_sync(0xffffffffu, my, j + 2);
                int s3 = __shfl_sync(0xffffffffu, my, j + 3);
                uint2 p0 = *(const uint2*)&d_hLb[(size_t)s0 * HID + lane * 4];
                uint2 p1 = *(const uint2*)&d_hLb[(size_t)s1 * HID + lane * 4];
                uint2 p2 = *(const uint2*)&d_hLb[(size_t)s2 * HID + lane * 4];
                uint2 p3 = *(const uint2*)&d_hLb[(size_t)s3 * HID + lane * 4];
                float2 f;
                f = __bfloat1622float2(*(__nv_bfloat162*)&p0.x); a0.x += f.x; a0.y += f.y;
                f = __bfloat1622float2(*(__nv_bfloat162*)&p0.y); a0.z += f.x; a0.w += f.y;
                f = __bfloat1622float2(*(__nv_bfloat162*)&p1.x); a1.x += f.x; a1.y += f.y;
                f = __bfloat1622float2(*(__nv_bfloat162*)&p1.y); a1.z += f.x; a1.w += f.y;
                f = __bfloat1622float2(*(__nv_bfloat162*)&p2.x); a2.x += f.x; a2.y += f.y;
                f = __bfloat1622float2(*(__nv_bfloat162*)&p2.y); a2.z += f.x; a2.w += f.y;
                f = __bfloat1622float2(*(__nv_bfloat162*)&p3.x); a3.x += f.x; a3.y += f.y;
                f = __bfloat1622float2(*(__nv_bfloat162*)&p3.y); a3.z += f.x; a3.w += f.y;
            }
            for (; j < cnt; j++) {
                int s = __shfl_sync(0xffffffffu, my, j);
                uint2 p = *(const uint2*)&d_hLb[(size_t)s * HID + lane * 4];
                float2 f;
                f = __bfloat1622float2(*(__nv_bfloat162*)&p.x); a0.x += f.x; a0.y += f.y;
                f = __bfloat1622float2(*(__nv_bfloat162*)&p.y); a0.z += f.x; a0.w += f.y;
            }
        }
        float4 acc;
        acc.x = (a0.x + a1.x) + (a2.x + a3.x);
        acc.y = (a0.y + a1.y) + (a2.y + a3.y);
        acc.z = (a0.z + a1.z) + (a2.z + a3.z);
        acc.w = (a0.w + a1.w) + (a2.w + a3.w);

        float inv = 1.f / fmaxf((float)deg, 1.f);
        float4 hr = HR4[(size_t)node * 32 + lane];
        float4 y;
        y.x = fmaf(acc.x, inv, hr.x);
        y.y = fmaf(acc.y, inv, hr.y);
        y.z = fmaf(acc.z, inv, hr.z);
        y.w = fmaf(acc.w, inv, hr.w);

        float s1 = y.x + y.y + y.z + y.w;
        float s2 = y.x * y.x + y.y * y.y + y.z * y.z + y.w * y.w;
        #pragma unroll
        for (int o = 16; o > 0; o >>= 1) {
            s1 += __shfl_xor_sync(0xffffffffu, s1, o);
            s2 += __shfl_xor_sync(0xffffffffu, s2, o);
        }
        float mu   = s1 * (1.f / 128.f);
        float var  = s2 * (1.f / 128.f) - mu * mu;
        float rstd = rsqrtf(var + 1e-5f);

        pacc.x += fmaxf((y.x - mu) * rstd * g4.x + b4.x, 0.f);
        pacc.y += fmaxf((y.y - mu) * rstd * g4.y + b4.y, 0.f);
        pacc.z += fmaxf((y.z - mu) * rstd * g4.z + b4.z, 0.f);
        pacc.w += fmaxf((y.w - mu) * rstd * g4.w + b4.w, 0.f);
    }

    __shared__ float sp[8][128];
    ((float4*)sp[warp])[lane] = pacc;
    __syncthreads();
    int t = threadIdx.x;
    if (t < HID) {
        float s = 0.f;
        #pragma unroll
        for (int w = 0; w < 8; w++) s += sp[w][t];
        atomicAdd(&d_pool[t], s);
    }
}

// ================= K5: final linear =================
__global__ void final_kernel(const float* __restrict__ ow,
                             const float* __restrict__ ob,
                             float* __restrict__ out)
{
    __shared__ float g[128];
    int t = threadIdx.x;
    g[t] = d_pool[t] * (1.f / (float)NN);
    __syncthreads();
    float s = ob[t];
    #pragma unroll 8
    for (int f = 0; f < 128; f++)
        s = fmaf(g[f], ow[(size_t)t * 128 + f], s);
    out[t] = s;
}

// ================= launch =================
extern "C" void kernel_launch(void* const* d_in, const int* in_sizes, int n_in,
                              void* d_out, int out_size)
{
    const float* x       = (const float*)d_in[0];
    const int*   ei      = (const int*)d_in[1];
    const float* proj_w  = (const float*)d_in[2];
    const float* proj_b  = (const float*)d_in[3];
    const float* lin_l_w = (const float*)d_in[4];
    const float* lin_l_b = (const float*)d_in[5];
    const float* lin_r_w = (const float*)d_in[6];
    const float* ln_g    = (const float*)d_in[7];
    const float* ln_b    = (const float*)d_in[8];
    const float* out_w   = (const float*)d_in[9];
    const float* out_b   = (const float*)d_in[10];
    float* out = (float*)d_out;

    static bool attr_done = false;
    if (!attr_done) {
        cudaFuncSetAttribute(proj_mma_kernel,    cudaFuncAttributeMaxDynamicSharedMemorySize, K1_SMEM);
        cudaFuncSetAttribute(combine_mma_kernel, cudaFuncAttributeMaxDynamicSharedMemorySize, K2_SMEM);
        attr_done = true;
    }

    zero_kernel<<<(NN + 255) / 256, 256>>>();
    presplit_kernel<<<160, 256>>>(proj_w, lin_l_w, lin_r_w);
    proj_mma_kernel<<<NBLK, 512, K1_SMEM>>>(x, proj_b);
    combine_mma_kernel<<<NBLK, 512, K2_SMEM>>>(lin_l_b);
    edge_bucket_kernel<<<(NEDGE + 255) / 256, 256>>>(ei);
    gather_ln_pool_kernel<<<592, 256>>>(ln_g, ln_b);
    final_kernel<<<1, 128>>>(out_w, out_b, out);
}

// round 8
// speedup vs baseline: 2.7717x; 1.0599x over previous
#include <cuda_runtime.h>
#include <cuda_bf16.h>
#include <stdint.h>

#define NN    50000
#define NEDGE 1600000
#define NDIM  1024
#define HID   128
#define CAP   128
#define NBLK  391   // ceil(NN/128)

// ================= scratch =================
__device__ uint8_t d_pwT[16][2][16384];          // proj_w  [ch][hl][tile] (32KB per chunk)
__device__ uint8_t d_wT [2][2][2][16384];        // [w L/R][hl][ch][tile]  (64KB per w)
__device__ __nv_bfloat16 d_hLb[(size_t)NN * HID];
__device__ float         d_hR [(size_t)NN * HID];
__device__ int           d_cnt[NN];
__device__ int           d_slot[(size_t)NN * CAP];
__device__ float         d_pool[HID];

// ================= helpers =================
__device__ __forceinline__ uint32_t smem_u32(const void* p) {
    uint32_t a;
    asm("{ .reg .u64 t; cvta.to.shared.u64 t, %1; cvt.u32.u64 %0, t; }" : "=r"(a) : "l"(p));
    return a;
}
#define SWZ128(o) ((o) ^ (((o) >> 3) & 0x70))

__device__ __forceinline__ uint32_t packbf2(__nv_bfloat16 a, __nv_bfloat16 b) {
    return (uint32_t)__bfloat16_as_ushort(a) | ((uint32_t)__bfloat16_as_ushort(b) << 16);
}
__device__ __forceinline__ void split4(float4 v, uint2& hi, uint2& lo) {
    __nv_bfloat16 hx = __float2bfloat16(v.x), hy = __float2bfloat16(v.y);
    __nv_bfloat16 hz = __float2bfloat16(v.z), hw = __float2bfloat16(v.w);
    __nv_bfloat16 lx = __float2bfloat16(v.x - __bfloat162float(hx));
    __nv_bfloat16 ly = __float2bfloat16(v.y - __bfloat162float(hy));
    __nv_bfloat16 lz = __float2bfloat16(v.z - __bfloat162float(hz));
    __nv_bfloat16 lw = __float2bfloat16(v.w - __bfloat162float(hw));
    hi.x = packbf2(hx, hy); hi.y = packbf2(hz, hw);
    lo.x = packbf2(lx, ly); lo.y = packbf2(lz, lw);
}

#define LDSM_X4(r, a) \
    asm volatile("ldmatrix.sync.aligned.m8n8.x4.shared.b16 {%0,%1,%2,%3}, [%4];" \
        : "=r"((r)[0]), "=r"((r)[1]), "=r"((r)[2]), "=r"((r)[3]) : "r"(a))
#define LDSM_X2(r, a) \
    asm volatile("ldmatrix.sync.aligned.m8n8.x2.shared.b16 {%0,%1}, [%2];" \
        : "=r"((r)[0]), "=r"((r)[1]) : "r"(a))
#define MMA_BF16(d, a, b) \
    asm volatile("mma.sync.aligned.m16n8k16.row.col.f32.bf16.bf16.f32 " \
        "{%0,%1,%2,%3}, {%4,%5,%6,%7}, {%8,%9}, {%0,%1,%2,%3};" \
        : "+f"((d)[0]), "+f"((d)[1]), "+f"((d)[2]), "+f"((d)[3]) \
        : "r"((a)[0]), "r"((a)[1]), "r"((a)[2]), "r"((a)[3]), "r"((b)[0]), "r"((b)[1]))

#define CP_A16(dst, src) \
    asm volatile("cp.async.cg.shared.global [%0], [%1], 16;" :: "r"(dst), "l"(src))
#define CP_COMMIT() asm volatile("cp.async.commit_group;")
#define CP_WAIT0()  asm volatile("cp.async.wait_group 0;" ::: "memory")
#define CP_WAIT1()  asm volatile("cp.async.wait_group 1;" ::: "memory")

__device__ __forceinline__ uint32_t addrA(uint32_t base, int MI, int ks, int lane) {
    int row  = MI * 16 + (lane & 15);
    int kb   = ks * 32 + ((lane >> 4) << 4);
    return base + SWZ128((uint32_t)(row * 128 + kb));
}
__device__ __forceinline__ uint32_t addrB(uint32_t base, int NI, int ks, int lane) {
    int row = NI * 8 + (lane & 7);
    int kb  = ks * 32 + (((lane >> 3) & 1) << 4);
    return base + SWZ128((uint32_t)(row * 128 + kb));
}

// ================= K0 =================
__global__ void zero_kernel() {
    int i = blockIdx.x * blockDim.x + threadIdx.x;
    if (i < NN)  d_cnt[i] = 0;
    if (i < HID) d_pool[i] = 0.f;
}

// ================= Kp: pre-split weights =================
__global__ void presplit_kernel(const float* __restrict__ pw,
                                const float* __restrict__ wl,
                                const float* __restrict__ wr)
{
    int i = blockIdx.x * blockDim.x + threadIdx.x;
    if (i < 32768) {
        int n  = i >> 8;
        int k4 = (i & 255) << 2;
        int ch = k4 >> 6, kk = k4 & 63;
        float4 v = ((const float4*)pw)[i];
        uint2 hi, lo; split4(v, hi, lo);
        uint32_t sw = SWZ128((uint32_t)(n * 128 + kk * 2));
        *(uint2*)&d_pwT[ch][0][sw] = hi;
        *(uint2*)&d_pwT[ch][1][sw] = lo;
    } else if (i < 40960) {
        int j = i - 32768;
        int w = j >= 4096;
        if (w) j -= 4096;
        const float* W = w ? wr : wl;
        int n  = j >> 5;
        int k4 = (j & 31) << 2;
        int ch = k4 >> 6, kk = k4 & 63;
        float4 v = ((const float4*)W)[j];
        uint2 hi, lo; split4(v, hi, lo);
        uint32_t sw = SWZ128((uint32_t)(n * 128 + kk * 2));
        *(uint2*)&d_wT[w][0][ch][sw] = hi;
        *(uint2*)&d_wT[w][1][ch][sw] = lo;
    }
}

// ================= KF: fused h = relu(x@Wp^T+b); hL = h@WL^T; hR = h@WR^T + bL ==========
// smem (192KB):
//   A stage0: hi @ 0,      lo @ 16384     (after mainloop: h ch0 hi/lo)
//   A stage1: hi @ 32768,  lo @ 49152     (after mainloop: h ch1 hi/lo)
//   Wproj stage s: @ 65536 + s*32768  (hi 16K + lo 16K, contiguous from d_pwT[c])
//   WLR: @ 131072, 64KB  ([hl][ch] tiles, contiguous from d_wT[pass])
#define KF_SMEM 196608

__global__ __launch_bounds__(512, 1)
void fused_mma_kernel(const float* __restrict__ X, const float* __restrict__ bias,
                      const float* __restrict__ bL)
{
    extern __shared__ char smem[];
    const uint32_t sb = smem_u32(smem);
    const int tid  = threadIdx.x;
    const int lane = tid & 31;
    const int wid  = tid >> 5;        // 0..15
    const int wm   = wid & 3;         // 4 row groups of 32
    const int wn   = wid >> 2;        // 4 col groups of 32
    const int row0 = blockIdx.x * 128;

    float acc[2][4][4];
    #pragma unroll
    for (int i = 0; i < 2; i++)
        #pragma unroll
        for (int j = 0; j < 4; j++)
            #pragma unroll
            for (int q = 0; q < 4; q++) acc[i][j][q] = 0.f;

    // ---- prologue: X chunk0 -> regs; W0 cp.async; split+store chunk0 -> A0
    float4 xv[4];
    #pragma unroll
    for (int it = 0; it < 4; it++) {
        int e = tid + it * 512;
        int r = e >> 4, c4 = (e & 15) << 2;
        int gm = row0 + r;
        xv[it] = (gm < NN) ? *(const float4*)&X[(size_t)gm * NDIM + c4]
                           : make_float4(0.f, 0.f, 0.f, 0.f);
    }
    {
        uint32_t wst = sb + 65536;
        const uint8_t* src = &d_pwT[0][0][0];
        #pragma unroll
        for (int q = 0; q < 4; q++)
            CP_A16(wst + tid * 16 + q * 8192, src + tid * 16 + q * 8192);
        CP_COMMIT();
    }
    #pragma unroll
    for (int it = 0; it < 4; it++) {
        int e = tid + it * 512;
        int r = e >> 4, c4 = (e & 15) << 2;
        uint2 hi, lo; split4(xv[it], hi, lo);
        uint32_t sw = SWZ128((uint32_t)(r * 128 + c4 * 2));
        *(uint2*)(smem + sw)         = hi;
        *(uint2*)(smem + 16384 + sw) = lo;
    }

    // ---- mainloop over 16 K-chunks
    #pragma unroll 1
    for (int c = 0; c < 16; c++) {
        const int s = c & 1;
        if (c < 15) {
            uint32_t wst = sb + 65536 + ((c + 1) & 1) * 32768;
            const uint8_t* src = &d_pwT[c + 1][0][0];
            #pragma unroll
            for (int q = 0; q < 4; q++)
                CP_A16(wst + tid * 16 + q * 8192, src + tid * 16 + q * 8192);
            CP_COMMIT();
            CP_WAIT1();
        } else {
            // prefetch WL for the fused passes; overlaps last chunk's MMAs
            uint32_t wlr = sb + 131072;
            const uint8_t* src = &d_wT[0][0][0][0];
            #pragma unroll
            for (int q = 0; q < 8; q++)
                CP_A16(wlr + tid * 16 + q * 8192, src + tid * 16 + q * 8192);
            CP_COMMIT();
            CP_WAIT1();   // Wproj chunk 15 done; WL may be pending
        }
        __syncthreads();

        if (c < 15) {
            const int kc = (c + 1) * 64;
            #pragma unroll
            for (int it = 0; it < 4; it++) {
                int e = tid + it * 512;
                int r = e >> 4, c4 = (e & 15) << 2;
                int gm = row0 + r;
                xv[it] = (gm < NN) ? *(const float4*)&X[(size_t)gm * NDIM + kc + c4]
                                   : make_float4(0.f, 0.f, 0.f, 0.f);
            }
        }

        const uint32_t aHi = sb + s * 32768, aLo = aHi + 16384;
        const uint32_t bHi = sb + 65536 + s * 32768, bLo = bHi + 16384;
        #pragma unroll
        for (int ks = 0; ks < 4; ks++) {
            uint32_t ahi[2][4], alo[2][4];
            #pragma unroll
            for (int mi = 0; mi < 2; mi++) {
                LDSM_X4(ahi[mi], addrA(aHi, wm * 2 + mi, ks, lane));
                LDSM_X4(alo[mi], addrA(aLo, wm * 2 + mi, ks, lane));
            }
            #pragma unroll
            for (int ni = 0; ni < 4; ni++) {
                uint32_t bh[2], bl[2];
                LDSM_X2(bh, addrB(bHi, wn * 4 + ni, ks, lane));
                LDSM_X2(bl, addrB(bLo, wn * 4 + ni, ks, lane));
                #pragma unroll
                for (int mi = 0; mi < 2; mi++) {
                    MMA_BF16(acc[mi][ni], ahi[mi], bh);
                    MMA_BF16(acc[mi][ni], ahi[mi], bl);
                    MMA_BF16(acc[mi][ni], alo[mi], bh);
                }
            }
        }

        // split + store NEXT chunk into the other A stage (no sync needed)
        if (c < 15) {
            char* base = smem + ((c + 1) & 1) * 32768;
            #pragma unroll
            for (int it = 0; it < 4; it++) {
                int e = tid + it * 512;
                int r = e >> 4, c4 = (e & 15) << 2;
                uint2 hi, lo; split4(xv[it], hi, lo);
                uint32_t sw = SWZ128((uint32_t)(r * 128 + c4 * 2));
                *(uint2*)(base + sw)         = hi;
                *(uint2*)(base + 16384 + sw) = lo;
            }
        }
        __syncthreads();
    }

    // ---- h epilogue: bias+relu+split, store h tiles into A area
    //      layout: h ch  -> aHi = sb + ch*32768, aLo = +16384
    // (mainloop reads of A finished — last __syncthreads above)
    #pragma unroll
    for (int ni = 0; ni < 4; ni++) {
        int cc = wn * 32 + ni * 8 + (lane & 3) * 2;
        int ch = cc >> 6, kk = cc & 63;
        float b0 = bias[cc], b1 = bias[cc + 1];
        #pragma unroll
        for (int mi = 0; mi < 2; mi++) {
            int rl0 = wm * 32 + mi * 16 + (lane >> 2);
            #pragma unroll
            for (int half = 0; half < 2; half++) {
                int rl = rl0 + half * 8;
                float v0 = fmaxf(acc[mi][ni][half * 2 + 0] + b0, 0.f);
                float v1 = fmaxf(acc[mi][ni][half * 2 + 1] + b1, 0.f);
                __nv_bfloat16 h0 = __float2bfloat16(v0), h1 = __float2bfloat16(v1);
                __nv_bfloat16 l0 = __float2bfloat16(v0 - __bfloat162float(h0));
                __nv_bfloat16 l1 = __float2bfloat16(v1 - __bfloat162float(h1));
                uint32_t sw = SWZ128((uint32_t)(rl * 128 + kk * 2));
                *(uint32_t*)(smem + ch * 32768 + sw)         = packbf2(h0, h1);
                *(uint32_t*)(smem + ch * 32768 + 16384 + sw) = packbf2(l0, l1);
            }
        }
    }
    CP_WAIT0();        // WL arrived
    __syncthreads();   // h tiles visible to all

    // ---- pass 0: hL = h @ WL^T  (bf16 out)
    const uint32_t wlr = sb + 131072;
    float ac2[2][4][4];
    #pragma unroll
    for (int i = 0; i < 2; i++)
        #pragma unroll
        for (int j = 0; j < 4; j++)
            #pragma unroll
            for (int q = 0; q < 4; q++) ac2[i][j][q] = 0.f;

    #pragma unroll
    for (int ks8 = 0; ks8 < 8; ks8++) {
        const int ch = ks8 >> 2, ks = ks8 & 3;
        const uint32_t aHi = sb + ch * 32768, aLo = aHi + 16384;
        const uint32_t wHi = wlr + ch * 16384, wLo = wlr + 32768 + ch * 16384;
        uint32_t ahi[2][4], alo[2][4];
        #pragma unroll
        for (int mi = 0; mi < 2; mi++) {
            LDSM_X4(ahi[mi], addrA(aHi, wm * 2 + mi, ks, lane));
            LDSM_X4(alo[mi], addrA(aLo, wm * 2 + mi, ks, lane));
        }
        #pragma unroll
        for (int ni = 0; ni < 4; ni++) {
            uint32_t bh[2], bl[2];
            LDSM_X2(bh, addrB(wHi, wn * 4 + ni, ks, lane));
            LDSM_X2(bl, addrB(wLo, wn * 4 + ni, ks, lane));
            #pragma unroll
            for (int mi = 0; mi < 2; mi++) {
                MMA_BF16(ac2[mi][ni], ahi[mi], bh);
                MMA_BF16(ac2[mi][ni], ahi[mi], bl);
                MMA_BF16(ac2[mi][ni], alo[mi], bh);
            }
        }
    }
    __syncthreads();   // all reads of WL done before overwrite

    // cp.async WR over WLR; overlap with hL global stores
    {
        const uint8_t* src = &d_wT[1][0][0][0];
        #pragma unroll
        for (int q = 0; q < 8; q++)
            CP_A16(wlr + tid * 16 + q * 8192, src + tid * 16 + q * 8192);
        CP_COMMIT();
    }
    #pragma unroll
    for (int ni = 0; ni < 4; ni++) {
        int cc = wn * 32 + ni * 8 + (lane & 3) * 2;
        #pragma unroll
        for (int mi = 0; mi < 2; mi++) {
            int r0 = row0 + wm * 32 + mi * 16 + (lane >> 2);
            #pragma unroll
            for (int half = 0; half < 2; half++) {
                int r = r0 + half * 8;
                if (r < NN) {
                    *(uint32_t*)&d_hLb[(size_t)r * HID + cc] =
                        packbf2(__float2bfloat16(ac2[mi][ni][half * 2 + 0]),
                                __float2bfloat16(ac2[mi][ni][half * 2 + 1]));
                }
            }
        }
    }
    CP_WAIT0();
    __syncthreads();

    // ---- pass 1: hR = h @ WR^T + bL  (f32 out)
    #pragma unroll
    for (int i = 0; i < 2; i++)
        #pragma unroll
        for (int j = 0; j < 4; j++)
            #pragma unroll
            for (int q = 0; q < 4; q++) ac2[i][j][q] = 0.f;

    #pragma unroll
    for (int ks8 = 0; ks8 < 8; ks8++) {
        const int ch = ks8 >> 2, ks = ks8 & 3;
        const uint32_t aHi = sb + ch * 32768, aLo = aHi + 16384;
        const uint32_t wHi = wlr + ch * 16384, wLo = wlr + 32768 + ch * 16384;
        uint32_t ahi[2][4], alo[2][4];
        #pragma unroll
        for (int mi = 0; mi < 2; mi++) {
            LDSM_X4(ahi[mi], addrA(aHi, wm * 2 + mi, ks, lane));
            LDSM_X4(alo[mi], addrA(aLo, wm * 2 + mi, ks, lane));
        }
        #pragma unroll
        for (int ni = 0; ni < 4; ni++) {
            uint32_t bh[2], bl[2];
            LDSM_X2(bh, addrB(wHi, wn * 4 + ni, ks, lane));
            LDSM_X2(bl, addrB(wLo, wn * 4 + ni, ks, lane));
            #pragma unroll
            for (int mi = 0; mi < 2; mi++) {
                MMA_BF16(ac2[mi][ni], ahi[mi], bh);
                MMA_BF16(ac2[mi][ni], ahi[mi], bl);
                MMA_BF16(ac2[mi][ni], alo[mi], bh);
            }
        }
    }
    #pragma unroll
    for (int ni = 0; ni < 4; ni++) {
        int cc = wn * 32 + ni * 8 + (lane & 3) * 2;
        float b0 = bL[cc], b1 = bL[cc + 1];
        #pragma unroll
        for (int mi = 0; mi < 2; mi++) {
            int r0 = row0 + wm * 32 + mi * 16 + (lane >> 2);
            #pragma unroll
            for (int half = 0; half < 2; half++) {
                int r = r0 + half * 8;
                if (r < NN) {
                    *(float2*)&d_hR[(size_t)r * HID + cc] =
                        make_float2(ac2[mi][ni][half * 2 + 0] + b0,
                                    ac2[mi][ni][half * 2 + 1] + b1);
                }
            }
        }
    }
}

// ================= K3: bucket edges by dst =================
__global__ void edge_bucket_kernel(const int* __restrict__ ei) {
    int i = blockIdx.x * blockDim.x + threadIdx.x;
    if (i >= NEDGE) return;
    int src = ei[i];
    int dst = ei[NEDGE + i];
    if ((unsigned)src >= NN || (unsigned)dst >= NN) return;
    int pos = atomicAdd(&d_cnt[dst], 1);
    if (pos < CAP) d_slot[(size_t)dst * CAP + pos] = src;
}

// ================= K4: gather + combine + LN + relu + pool =================
__global__ __launch_bounds__(256)
void gather_ln_pool_kernel(const float* __restrict__ lng,
                           const float* __restrict__ lnb)
{
    const int lane   = threadIdx.x & 31;
    const int warp   = threadIdx.x >> 5;
    const int nwarps = blockDim.x >> 5;

    const float4* HR4 = (const float4*)d_hR;
    const float4  g4  = ((const float4*)lng)[lane];
    const float4  b4  = ((const float4*)lnb)[lane];

    float4 pacc = make_float4(0.f, 0.f, 0.f, 0.f);

    for (int node = blockIdx.x * nwarps + warp; node < NN;
         node += gridDim.x * nwarps)
    {
        int deg = d_cnt[node];
        int dn  = min(deg, CAP);

        int sl[4];
        #pragma unroll
        for (int q = 0; q < 4; q++) {
            int idx = q * 32 + lane;
            sl[q] = (idx < dn) ? d_slot[(size_t)node * CAP + idx] : 0;
        }

        float4 a0 = make_float4(0.f, 0.f, 0.f, 0.f);
        float4 a1 = make_float4(0.f, 0.f, 0.f, 0.f);
        float4 a2 = make_float4(0.f, 0.f, 0.f, 0.f);
        float4 a3 = make_float4(0.f, 0.f, 0.f, 0.f);

        #pragma unroll
        for (int q = 0; q < 4; q++) {
            int base = q * 32;
            if (base >= dn) break;
            int cnt = min(32, dn - base);
            int my  = sl[q];
            int j = 0;
            #pragma unroll 2
            for (; j + 4 <= cnt; j += 4) {
                int s0 = __shfl_sync(0xffffffffu, my, j + 0);
                int s1 = __shfl_sync(0xffffffffu, my, j + 1);
                int s2 = __shfl_sync(0xffffffffu, my, j + 2);
                int s3 = __shfl_sync(0xffffffffu, my, j + 3);
                uint2 p0 = *(const uint2*)&d_hLb[(size_t)s0 * HID + lane * 4];
                uint2 p1 = *(const uint2*)&d_hLb[(size_t)s1 * HID + lane * 4];
                uint2 p2 = *(const uint2*)&d_hLb[(size_t)s2 * HID + lane * 4];
                uint2 p3 = *(const uint2*)&d_hLb[(size_t)s3 * HID + lane * 4];
                float2 f;
                f = __bfloat1622float2(*(__nv_bfloat162*)&p0.x); a0.x += f.x; a0.y += f.y;
                f = __bfloat1622float2(*(__nv_bfloat162*)&p0.y); a0.z += f.x; a0.w += f.y;
                f = __bfloat1622float2(*(__nv_bfloat162*)&p1.x); a1.x += f.x; a1.y += f.y;
                f = __bfloat1622float2(*(__nv_bfloat162*)&p1.y); a1.z += f.x; a1.w += f.y;
                f = __bfloat1622float2(*(__nv_bfloat162*)&p2.x); a2.x += f.x; a2.y += f.y;
                f = __bfloat1622float2(*(__nv_bfloat162*)&p2.y); a2.z += f.x; a2.w += f.y;
                f = __bfloat1622float2(*(__nv_bfloat162*)&p3.x); a3.x += f.x; a3.y += f.y;
                f = __bfloat1622float2(*(__nv_bfloat162*)&p3.y); a3.z += f.x; a3.w += f.y;
            }
            for (; j < cnt; j++) {
                int s = __shfl_sync(0xffffffffu, my, j);
                uint2 p = *(const uint2*)&d_hLb[(size_t)s * HID + lane * 4];
                float2 f;
                f = __bfloat1622float2(*(__nv_bfloat162*)&p.x); a0.x += f.x; a0.y += f.y;
                f = __bfloat1622float2(*(__nv_bfloat162*)&p.y); a0.z += f.x; a0.w += f.y;
            }
        }
        float4 acc;
        acc.x = (a0.x + a1.x) + (a2.x + a3.x);
        acc.y = (a0.y + a1.y) + (a2.y + a3.y);
        acc.z = (a0.z + a1.z) + (a2.z + a3.z);
        acc.w = (a0.w + a1.w) + (a2.w + a3.w);

        float inv = 1.f / fmaxf((float)deg, 1.f);
        float4 hr = HR4[(size_t)node * 32 + lane];
        float4 y;
        y.x = fmaf(acc.x, inv, hr.x);
        y.y = fmaf(acc.y, inv, hr.y);
        y.z = fmaf(acc.z, inv, hr.z);
        y.w = fmaf(acc.w, inv, hr.w);

        float s1 = y.x + y.y + y.z + y.w;
        float s2 = y.x * y.x + y.y * y.y + y.z * y.z + y.w * y.w;
        #pragma unroll
        for (int o = 16; o > 0; o >>= 1) {
            s1 += __shfl_xor_sync(0xffffffffu, s1, o);
            s2 += __shfl_xor_sync(0xffffffffu, s2, o);
        }
        float mu   = s1 * (1.f / 128.f);
        float var  = s2 * (1.f / 128.f) - mu * mu;
        float rstd = rsqrtf(var + 1e-5f);

        pacc.x += fmaxf((y.x - mu) * rstd * g4.x + b4.x, 0.f);
        pacc.y += fmaxf((y.y - mu) * rstd * g4.y + b4.y, 0.f);
        pacc.z += fmaxf((y.z - mu) * rstd * g4.z + b4.z, 0.f);
        pacc.w += fmaxf((y.w - mu) * rstd * g4.w + b4.w, 0.f);
    }

    __shared__ float sp[8][128];
    ((float4*)sp[warp])[lane] = pacc;
    __syncthreads();
    int t = threadIdx.x;
    if (t < HID) {
        float s = 0.f;
        #pragma unroll
        for (int w = 0; w < 8; w++) s += sp[w][t];
        atomicAdd(&d_pool[t], s);
    }
}

// ================= K5: final linear =================
__global__ void final_kernel(const float* __restrict__ ow,
                             const float* __restrict__ ob,
                             float* __restrict__ out)
{
    __shared__ float g[128];
    int t = threadIdx.x;
    g[t] = d_pool[t] * (1.f / (float)NN);
    __syncthreads();
    float s = ob[t];
    #pragma unroll 8
    for (int f = 0; f < 128; f++)
        s = fmaf(g[f], ow[(size_t)t * 128 + f], s);
    out[t] = s;
}

// ================= launch =================
extern "C" void kernel_launch(void* const* d_in, const int* in_sizes, int n_in,
                              void* d_out, int out_size)
{
    const float* x       = (const float*)d_in[0];
    const int*   ei      = (const int*)d_in[1];
    const float* proj_w  = (const float*)d_in[2];
    const float* proj_b  = (const float*)d_in[3];
    const float* lin_l_w = (const float*)d_in[4];
    const float* lin_l_b = (const float*)d_in[5];
    const float* lin_r_w = (const float*)d_in[6];
    const float* ln_g    = (const float*)d_in[7];
    const float* ln_b    = (const float*)d_in[8];
    const float* out_w   = (const float*)d_in[9];
    const float* out_b   = (const float*)d_in[10];
    float* out = (float*)d_out;

    static bool attr_done = false;
    if (!attr_done) {
        cudaFuncSetAttribute(fused_mma_kernel, cudaFuncAttributeMaxDynamicSharedMemorySize, KF_SMEM);
        attr_done = true;
    }

    zero_kernel<<<(NN + 255) / 256, 256>>>();
    presplit_kernel<<<160, 256>>>(proj_w, lin_l_w, lin_r_w);
    fused_mma_kernel<<<NBLK, 512, KF_SMEM>>>(x, proj_b, lin_l_b);
    edge_bucket_kernel<<<(NEDGE + 255) / 256, 256>>>(ei);
    gather_ln_pool_kernel<<<592, 256>>>(ln_g, ln_b);
    final_kernel<<<1, 128>>>(out_w, out_b, out);
}